// round 1
// baseline (speedup 1.0000x reference)
#include <cuda_runtime.h>
#include <math.h>

#define N_NODES 50000
#define E_EDGES 600000
#define IN_DIM_ 512
#define HID_ 256
#define OUT_DIM_ 64

// ---------------- scratch (static device globals; no allocations) ----------
__device__ float g_hp1[(size_t)N_NODES * HID_];    // features @ W1
__device__ float g_h1acc[(size_t)N_NODES * HID_];  // propagate 1 accumulator
__device__ float g_hp3[(size_t)N_NODES * HID_];    // h2 @ W2^T
__device__ float g_h3acc[(size_t)N_NODES * HID_];  // propagate 2 accumulator
__device__ float g_as[N_NODES];
__device__ float g_ad[N_NODES];
__device__ float g_m[N_NODES];
__device__ float g_denom[N_NODES];
__device__ float g_ew[E_EDGES];                    // unnormalized exp weights

// ---------------- helpers ---------------------------------------------------
__device__ __forceinline__ float elu_f(float x) {
    return x > 0.f ? x : (expf(x) - 1.f);
}

__device__ __forceinline__ void atomicMaxFloat(float* addr, float val) {
    if (val >= 0.f) {
        atomicMax((int*)addr, __float_as_int(val));
    } else {
        atomicMin((unsigned int*)addr, __float_as_uint(val));
    }
}

// ---------------- init ------------------------------------------------------
__global__ void init_bufs(float* acc1, float* acc3, float* m, float* denom) {
    size_t i = (size_t)blockIdx.x * blockDim.x + threadIdx.x;
    size_t stride = (size_t)gridDim.x * blockDim.x;
    size_t accN4 = (size_t)N_NODES * HID_ / 4;
    float4 z = make_float4(0.f, 0.f, 0.f, 0.f);
    for (size_t t = i; t < accN4; t += stride) {
        ((float4*)acc1)[t] = z;
        ((float4*)acc3)[t] = z;
    }
    for (size_t t = i; t < N_NODES; t += stride) {
        m[t] = -INFINITY;
        denom[t] = 0.f;
    }
}

// ---------------- tiled SGEMM ----------------------------------------------
// C[M,N] = op(A)[M,K] * op(B)[K,N]
// A is row-major [M,K]; if ELUA, apply elu elementwise to A on load.
// If TRANSB, B is row-major [N,K] and we use B^T; else B is row-major [K,N].
template <int BM, int BN, int BK, int TM, int TN, bool TRANSB, bool ELUA>
__global__ void __launch_bounds__((BM / TM) * (BN / TN))
sgemm_kernel(const float* __restrict__ A, const float* __restrict__ B,
             float* __restrict__ C, int M, int N, int K) {
    constexpr int NT = (BM / TM) * (BN / TN);
    __shared__ float As[BK][BM];
    __shared__ float Bs[BK][BN];

    const int tid = threadIdx.x;
    const int rowBase = blockIdx.y * BM;
    const int colBase = blockIdx.x * BN;
    const int tx = tid % (BN / TN);
    const int ty = tid / (BN / TN);

    float acc[TM][TN];
#pragma unroll
    for (int i = 0; i < TM; i++)
#pragma unroll
        for (int j = 0; j < TN; j++) acc[i][j] = 0.f;

    for (int k0 = 0; k0 < K; k0 += BK) {
        // ---- load A tile (BM x BK), store transposed As[k][m] ----
#pragma unroll
        for (int t = tid; t < BM * BK / 4; t += NT) {
            int m = t / (BK / 4);
            int kq = t % (BK / 4);
            int row = rowBase + m;
            float4 v = make_float4(0.f, 0.f, 0.f, 0.f);
            if (row < M)
                v = *(const float4*)(A + (size_t)row * K + k0 + kq * 4);
            if (ELUA) {
                v.x = elu_f(v.x); v.y = elu_f(v.y);
                v.z = elu_f(v.z); v.w = elu_f(v.w);
            }
            As[kq * 4 + 0][m] = v.x;
            As[kq * 4 + 1][m] = v.y;
            As[kq * 4 + 2][m] = v.z;
            As[kq * 4 + 3][m] = v.w;
        }
        // ---- load B tile ----
        if (!TRANSB) {
#pragma unroll
            for (int t = tid; t < BK * BN / 4; t += NT) {
                int k = t / (BN / 4);
                int nq = t % (BN / 4);
                float4 v = *(const float4*)(B + (size_t)(k0 + k) * N + colBase + nq * 4);
                *(float4*)&Bs[k][nq * 4] = v;
            }
        } else {
#pragma unroll
            for (int t = tid; t < BN * BK / 4; t += NT) {
                int n = t / (BK / 4);
                int kq = t % (BK / 4);
                float4 v = *(const float4*)(B + (size_t)(colBase + n) * K + k0 + kq * 4);
                Bs[kq * 4 + 0][n] = v.x;
                Bs[kq * 4 + 1][n] = v.y;
                Bs[kq * 4 + 2][n] = v.z;
                Bs[kq * 4 + 3][n] = v.w;
            }
        }
        __syncthreads();

        // ---- compute ----
#pragma unroll
        for (int k = 0; k < BK; k++) {
            float ra[TM], rb[TN];
#pragma unroll
            for (int i = 0; i < TM; i += 4) {
                float4 t4 = *(const float4*)&As[k][ty * TM + i];
                ra[i] = t4.x; ra[i + 1] = t4.y; ra[i + 2] = t4.z; ra[i + 3] = t4.w;
            }
#pragma unroll
            for (int j = 0; j < TN; j += 4) {
                float4 t4 = *(const float4*)&Bs[k][tx * TN + j];
                rb[j] = t4.x; rb[j + 1] = t4.y; rb[j + 2] = t4.z; rb[j + 3] = t4.w;
            }
#pragma unroll
            for (int i = 0; i < TM; i++)
#pragma unroll
                for (int j = 0; j < TN; j++) acc[i][j] = fmaf(ra[i], rb[j], acc[i][j]);
        }
        __syncthreads();
    }

    // ---- store ----
#pragma unroll
    for (int i = 0; i < TM; i++) {
        int row = rowBase + ty * TM + i;
        if (row < M) {
#pragma unroll
            for (int j = 0; j < TN; j += 4) {
                float4 v = make_float4(acc[i][j], acc[i][j + 1], acc[i][j + 2], acc[i][j + 3]);
                *(float4*)(C + (size_t)row * N + colBase + tx * TN + j) = v;
            }
        }
    }
}

// ---------------- per-node attention dots ------------------------------------
__global__ void att_kernel(const float* __restrict__ hp1,
                           const float* __restrict__ asrc,
                           const float* __restrict__ adst,
                           float* __restrict__ a_s, float* __restrict__ a_d) {
    int warp = (blockIdx.x * blockDim.x + threadIdx.x) >> 5;
    int lane = threadIdx.x & 31;
    if (warp >= N_NODES) return;
    const float4* row = (const float4*)(hp1 + (size_t)warp * HID_);
    const float4* ws4 = (const float4*)asrc;
    const float4* wd4 = (const float4*)adst;
    float s = 0.f, d = 0.f;
#pragma unroll
    for (int i = 0; i < HID_ / 128; i++) {  // HID/4 float4s over 32 lanes
        float4 v = row[lane + i * 32];
        float4 ws = ws4[lane + i * 32];
        float4 wd = wd4[lane + i * 32];
        s += v.x * ws.x + v.y * ws.y + v.z * ws.z + v.w * ws.w;
        d += v.x * wd.x + v.y * wd.y + v.z * wd.z + v.w * wd.w;
    }
#pragma unroll
    for (int o = 16; o; o >>= 1) {
        s += __shfl_xor_sync(0xffffffffu, s, o);
        d += __shfl_xor_sync(0xffffffffu, d, o);
    }
    if (lane == 0) { a_s[warp] = s; a_d[warp] = d; }
}

// ---------------- edge passes -------------------------------------------------
__global__ void edge_logits_max(const int* __restrict__ src, const int* __restrict__ dst,
                                const float* __restrict__ a_s, const float* __restrict__ a_d,
                                float* __restrict__ ew, float* __restrict__ m) {
    int e = blockIdx.x * blockDim.x + threadIdx.x;
    if (e >= E_EDGES) return;
    int s = src[e], d = dst[e];
    float x = a_s[s] + a_d[d];
    x = x > 0.f ? x : 0.2f * x;  // leaky_relu, slope 0.2
    ew[e] = x;                   // store logit temporarily
    atomicMaxFloat(&m[d], x);
}

__global__ void edge_exp_sum(const int* __restrict__ dst,
                             float* __restrict__ ew,
                             const float* __restrict__ m,
                             float* __restrict__ denom) {
    int e = blockIdx.x * blockDim.x + threadIdx.x;
    if (e >= E_EDGES) return;
    int d = dst[e];
    float ex = expf(ew[e] - m[d]);
    ew[e] = ex;
    atomicAdd(&denom[d], ex);
}

// ---------------- weighted scatter-add ----------------------------------------
// one warp per edge; normalization w = ew / (denom + 1e-16) done inline
__global__ void scatter_edges(const int* __restrict__ src, const int* __restrict__ dst,
                              const float* __restrict__ ew, const float* __restrict__ denom,
                              const float* __restrict__ H, float* __restrict__ out) {
    int e = (blockIdx.x * blockDim.x + threadIdx.x) >> 5;
    int lane = threadIdx.x & 31;
    if (e >= E_EDGES) return;
    int s = src[e], d = dst[e];
    float we = ew[e] / (denom[d] + 1e-16f);
    const float4* hr = (const float4*)(H + (size_t)s * HID_);
    float* orow = out + (size_t)d * HID_;
#pragma unroll
    for (int i = 0; i < HID_ / 128; i++) {  // 64 float4 across 32 lanes
        int idx = lane + i * 32;
        float4 v = hr[idx];
        int c = idx * 4;
        atomicAdd(orow + c + 0, v.x * we);
        atomicAdd(orow + c + 1, v.y * we);
        atomicAdd(orow + c + 2, v.z * we);
        atomicAdd(orow + c + 3, v.w * we);
    }
}

// ---------------- launch ------------------------------------------------------
extern "C" void kernel_launch(void* const* d_in, const int* in_sizes, int n_in,
                              void* d_out, int out_size) {
    const float* features = (const float*)d_in[0];  // [N, 512]
    const float* W1       = (const float*)d_in[1];  // [512, 256]
    const float* W2       = (const float*)d_in[2];  // [256, 64]
    const float* att_src  = (const float*)d_in[3];  // [256]
    const float* att_dst  = (const float*)d_in[4];  // [256]
    const int*   edge     = (const int*)d_in[5];    // [2, E]
    const int* src = edge;
    const int* dst = edge + E_EDGES;

    float* out = (float*)d_out;
    float* h2 = out;                                      // [N, 64]
    float* h4 = out + (size_t)N_NODES * OUT_DIM_;         // [N, 512]

    float *hp1, *h1acc, *hp3, *h3acc, *a_s, *a_d, *m, *denom, *ew;
    cudaGetSymbolAddress((void**)&hp1,   g_hp1);
    cudaGetSymbolAddress((void**)&h1acc, g_h1acc);
    cudaGetSymbolAddress((void**)&hp3,   g_hp3);
    cudaGetSymbolAddress((void**)&h3acc, g_h3acc);
    cudaGetSymbolAddress((void**)&a_s,   g_as);
    cudaGetSymbolAddress((void**)&a_d,   g_ad);
    cudaGetSymbolAddress((void**)&m,     g_m);
    cudaGetSymbolAddress((void**)&denom, g_denom);
    cudaGetSymbolAddress((void**)&ew,    g_ew);

    // 0) init accumulators / softmax state
    init_bufs<<<1024, 256>>>(h1acc, h3acc, m, denom);

    // 1) hp1 = features @ W1   [50000,512]x[512,256]
    {
        dim3 grid(HID_ / 128, (N_NODES + 127) / 128);
        sgemm_kernel<128, 128, 16, 8, 8, false, false>
            <<<grid, 256>>>(features, W1, hp1, N_NODES, HID_, IN_DIM_);
    }

    // 2) a_s = hp1 @ att_src, a_d = hp1 @ att_dst
    att_kernel<<<(N_NODES * 32 + 255) / 256, 256>>>(hp1, att_src, att_dst, a_s, a_d);

    // 3) per-edge leaky-relu logits + segment max
    edge_logits_max<<<(E_EDGES + 255) / 256, 256>>>(src, dst, a_s, a_d, ew, m);

    // 4) exp + segment sum
    edge_exp_sum<<<(E_EDGES + 255) / 256, 256>>>(dst, ew, m, denom);

    // 5) propagate 1: h1acc[d] += hp1[s] * w
    scatter_edges<<<(E_EDGES * 32 + 255) / 256, 256>>>(src, dst, ew, denom, hp1, h1acc);

    // 6) h2 = elu(h1acc) @ W2   -> d_out[0 : N*64]
    {
        dim3 grid(OUT_DIM_ / 64, (N_NODES + 127) / 128);
        sgemm_kernel<128, 64, 16, 8, 4, false, true>
            <<<grid, 256>>>(h1acc, W2, h2, N_NODES, OUT_DIM_, HID_);
    }

    // 7) hp3 = h2 @ W2^T   [50000,64] x [64,256] (B = W2 [256,64], transposed)
    {
        dim3 grid(HID_ / 128, (N_NODES + 127) / 128);
        sgemm_kernel<128, 128, 16, 8, 8, true, false>
            <<<grid, 256>>>(h2, W2, hp3, N_NODES, HID_, OUT_DIM_);
    }

    // 8) propagate 2 (same attention weights): h3acc[d] += hp3[s] * w
    scatter_edges<<<(E_EDGES * 32 + 255) / 256, 256>>>(src, dst, ew, denom, hp3, h3acc);

    // 9) h4 = elu(h3acc) @ W1^T  [50000,256] x [256,512] (B = W1 [512,256], transposed)
    {
        dim3 grid(IN_DIM_ / 128, (N_NODES + 127) / 128);
        sgemm_kernel<128, 128, 16, 8, 8, true, true>
            <<<grid, 256>>>(h3acc, W1, h4, N_NODES, IN_DIM_, HID_);
    }

    (void)in_sizes; (void)n_in; (void)out_size;
}

// round 3
// speedup vs baseline: 1.3457x; 1.3457x over previous
#include <cuda_runtime.h>
#include <cuda_bf16.h>
#include <math.h>
#include <stdint.h>

#define N_NODES 50000
#define E_EDGES 600000
#define IN_DIM_ 512
#define HID_ 256
#define OUT_DIM_ 64

// ---------------- scratch (static device globals; no allocations) ----------
__device__ float g_hp1[(size_t)N_NODES * HID_];    // features @ W1
__device__ float g_h1acc[(size_t)N_NODES * HID_];  // propagate 1 accumulator
__device__ float g_hp3[(size_t)N_NODES * HID_];    // h2 @ W2^T
__device__ float g_h3acc[(size_t)N_NODES * HID_];  // propagate 2 accumulator
__device__ float g_as[N_NODES];
__device__ float g_ad[N_NODES];
__device__ float g_m[N_NODES];
__device__ float g_denom[N_NODES];
__device__ float g_ew[E_EDGES];                    // unnormalized exp weights

// prepped weight operands, B[n][k] layout (K-major rows), bf16 hi/lo split
__device__ __nv_bfloat16 g_b1hi[256 * 512], g_b1lo[256 * 512];  // W1^T view  (N=256,K=512)
__device__ __nv_bfloat16 g_b2hi[64 * 256],  g_b2lo[64 * 256];   // W2^T view  (N=64, K=256)
__device__ __nv_bfloat16 g_b3hi[256 * 64],  g_b3lo[256 * 64];   // W2 direct  (N=256,K=64)
__device__ __nv_bfloat16 g_b4hi[512 * 256], g_b4lo[512 * 256];  // W1 direct  (N=512,K=256)

// ---------------- helpers -----------------------------------------------------
__device__ __forceinline__ uint32_t smem_u32(const void* p) {
    uint32_t a;
    asm("{ .reg .u64 t; cvta.to.shared.u64 t, %1; cvt.u32.u64 %0, t; }" : "=r"(a) : "l"(p));
    return a;
}
__device__ __forceinline__ float elu_f(float x) {
    return x > 0.f ? x : (expf(x) - 1.f);
}
__device__ __forceinline__ void atomicMaxFloat(float* addr, float val) {
    if (val >= 0.f) atomicMax((int*)addr, __float_as_int(val));
    else            atomicMin((unsigned int*)addr, __float_as_uint(val));
}
__device__ __forceinline__ void split_bf16(float x, __nv_bfloat16& hi, __nv_bfloat16& lo) {
    hi = __float2bfloat16_rn(x);
    lo = __float2bfloat16_rn(x - __bfloat162float(hi));
}

__device__ __forceinline__ void ldsm_x4(uint32_t addr, uint32_t* r) {
    asm volatile("ldmatrix.sync.aligned.m8n8.x4.shared.b16 {%0,%1,%2,%3}, [%4];"
                 : "=r"(r[0]), "=r"(r[1]), "=r"(r[2]), "=r"(r[3]) : "r"(addr));
}
__device__ __forceinline__ void ldsm_x2(uint32_t addr, uint32_t* r) {
    asm volatile("ldmatrix.sync.aligned.m8n8.x2.shared.b16 {%0,%1}, [%2];"
                 : "=r"(r[0]), "=r"(r[1]) : "r"(addr));
}
__device__ __forceinline__ void mma_bf16(float* d, const uint32_t* a, const uint32_t* b) {
    asm volatile(
        "mma.sync.aligned.m16n8k16.row.col.f32.bf16.bf16.f32 "
        "{%0,%1,%2,%3}, {%4,%5,%6,%7}, {%8,%9}, {%0,%1,%2,%3};"
        : "+f"(d[0]), "+f"(d[1]), "+f"(d[2]), "+f"(d[3])
        : "r"(a[0]), "r"(a[1]), "r"(a[2]), "r"(a[3]), "r"(b[0]), "r"(b[1]));
}

// ---------------- init ----------------------------------------------------------
__global__ void init_bufs(float* acc1, float* acc3, float* m, float* denom) {
    size_t i = (size_t)blockIdx.x * blockDim.x + threadIdx.x;
    size_t stride = (size_t)gridDim.x * blockDim.x;
    size_t accN4 = (size_t)N_NODES * HID_ / 4;
    float4 z = make_float4(0.f, 0.f, 0.f, 0.f);
    for (size_t t = i; t < accN4; t += stride) {
        ((float4*)acc1)[t] = z;
        ((float4*)acc3)[t] = z;
    }
    for (size_t t = i; t < N_NODES; t += stride) {
        m[t] = -INFINITY;
        denom[t] = 0.f;
    }
}

// ---------------- weight prep: split + (transpose where needed) ------------------
__global__ void prep_weights(const float* __restrict__ W1, const float* __restrict__ W2,
                             __nv_bfloat16* b1hi, __nv_bfloat16* b1lo,
                             __nv_bfloat16* b2hi, __nv_bfloat16* b2lo,
                             __nv_bfloat16* b3hi, __nv_bfloat16* b3lo,
                             __nv_bfloat16* b4hi, __nv_bfloat16* b4lo) {
    int i = blockIdx.x * blockDim.x + threadIdx.x;
    if (i < 512 * 256) {  // W1[k][n]
        int k = i >> 8, n = i & 255;
        __nv_bfloat16 hi, lo;
        split_bf16(W1[i], hi, lo);
        b4hi[i] = hi;           b4lo[i] = lo;            // W1 direct  [512][256]
        b1hi[n * 512 + k] = hi; b1lo[n * 512 + k] = lo;  // W1^T       [256][512]
    }
    if (i < 256 * 64) {   // W2[k][n]
        int k = i >> 6, n = i & 63;
        __nv_bfloat16 hi, lo;
        split_bf16(W2[i], hi, lo);
        b3hi[i] = hi;           b3lo[i] = lo;            // W2 direct  [256][64]
        b2hi[n * 256 + k] = hi; b2lo[n * 256 + k] = lo;  // W2^T       [64][256]
    }
}

// ---------------- HMMA split-fp32 GEMM --------------------------------------------
// C[M,N] = op(A)[M,K] @ B, B prepped as [N][K] bf16 hi/lo rows.
// BM=128, BK=32. A fp32 split to bf16 hi/lo on the fly (optional fused elu).
// acc += Ahi*Bhi + Ahi*Blo + Alo*Bhi  (fp32 accum in registers).
template <int BN, bool ELUA>
__global__ void __launch_bounds__(256)
hmma_gemm(const float* __restrict__ A,
          const __nv_bfloat16* __restrict__ Bhi, const __nv_bfloat16* __restrict__ Blo,
          float* __restrict__ C, int M, int N, int K) {
    constexpr int SP = 40;              // padded row stride (bf16 elems) -> 80B
    constexpr int WN = BN / 4;          // warp tile N (warps: 2 in M x 4 in N)
    constexpr int MT = 4;               // 64 / 16
    constexpr int NT = WN / 8;

    __shared__ __nv_bfloat16 sAhi[128 * SP];
    __shared__ __nv_bfloat16 sAlo[128 * SP];
    __shared__ __nv_bfloat16 sBhi[BN * SP];
    __shared__ __nv_bfloat16 sBlo[BN * SP];

    const int tid = threadIdx.x;
    const int wid = tid >> 5;
    const int lane = tid & 31;
    const int wm = wid >> 2;            // 0..1
    const int wn = wid & 3;             // 0..3

    const int rowBase = blockIdx.y * 128;
    const int colBase = blockIdx.x * BN;

    const uint32_t sAhi_b = smem_u32(sAhi);
    const uint32_t sAlo_b = smem_u32(sAlo);
    const uint32_t sBhi_b = smem_u32(sBhi);
    const uint32_t sBlo_b = smem_u32(sBlo);

    float acc[MT][NT][4];
#pragma unroll
    for (int i = 0; i < MT; i++)
#pragma unroll
        for (int j = 0; j < NT; j++)
#pragma unroll
            for (int c = 0; c < 4; c++) acc[i][j][c] = 0.f;

    // precomputed ldmatrix lane addressing
    const int aq = lane >> 3;                       // quadrant
    const int a_row_in = (aq & 1) * 8 + (lane & 7); // within 16-row tile
    const int a_col_off = (aq >> 1) * 8;
    const int b_row_in = lane & 7;
    const int b_col_off = ((lane >> 3) & 1) * 8;

    for (int k0 = 0; k0 < K; k0 += 32) {
        // ---- A tile fill: 128x32 fp32 -> hi/lo bf16 ----
#pragma unroll
        for (int i = 0; i < 4; i++) {
            int u = tid + i * 256;          // 1024 float4 slots
            int r = u >> 3;
            int q = u & 7;
            int grow = rowBase + r;
            float4 v = make_float4(0.f, 0.f, 0.f, 0.f);
            if (grow < M) v = *(const float4*)(A + (size_t)grow * K + k0 + q * 4);
            if (ELUA) {
                v.x = elu_f(v.x); v.y = elu_f(v.y);
                v.z = elu_f(v.z); v.w = elu_f(v.w);
            }
            __nv_bfloat16 hx, lx, hy, ly, hz, lz, hw, lw;
            split_bf16(v.x, hx, lx); split_bf16(v.y, hy, ly);
            split_bf16(v.z, hz, lz); split_bf16(v.w, hw, lw);
            __nv_bfloat162 h01 = __nv_bfloat162(hx, hy), h23 = __nv_bfloat162(hz, hw);
            __nv_bfloat162 l01 = __nv_bfloat162(lx, ly), l23 = __nv_bfloat162(lz, lw);
            *(uint2*)&sAhi[r * SP + q * 4] = make_uint2(*(uint32_t*)&h01, *(uint32_t*)&h23);
            *(uint2*)&sAlo[r * SP + q * 4] = make_uint2(*(uint32_t*)&l01, *(uint32_t*)&l23);
        }
        // ---- B tile fill: BNx32 bf16 x2 ----
#pragma unroll
        for (int i = 0; i < BN / 64; i++) {
            int u = tid + i * 256;          // BN*4 uint4 slots per buffer
            int r = u >> 2;
            int q = u & 3;
            size_t gidx = (size_t)(colBase + r) * K + k0 + q * 8;
            *(uint4*)&sBhi[r * SP + q * 8] = *(const uint4*)(Bhi + gidx);
            *(uint4*)&sBlo[r * SP + q * 8] = *(const uint4*)(Blo + gidx);
        }
        __syncthreads();

        // ---- compute: 2 k-steps of 16 ----
#pragma unroll
        for (int ks = 0; ks < 2; ks++) {
            uint32_t ahi[MT][4], alo[MT][4];
#pragma unroll
            for (int mt = 0; mt < MT; mt++) {
                int row = wm * 64 + mt * 16 + a_row_in;
                int col = ks * 16 + a_col_off;
                uint32_t off = (uint32_t)(row * SP + col) * 2;
                ldsm_x4(sAhi_b + off, ahi[mt]);
                ldsm_x4(sAlo_b + off, alo[mt]);
            }
            uint32_t bhi[NT][2], blo[NT][2];
#pragma unroll
            for (int nt = 0; nt < NT; nt++) {
                int row = wn * WN + nt * 8 + b_row_in;
                int col = ks * 16 + b_col_off;
                uint32_t off = (uint32_t)(row * SP + col) * 2;
                ldsm_x2(sBhi_b + off, bhi[nt]);
                ldsm_x2(sBlo_b + off, blo[nt]);
            }
#pragma unroll
            for (int mt = 0; mt < MT; mt++)
#pragma unroll
                for (int nt = 0; nt < NT; nt++) {
                    mma_bf16(acc[mt][nt], ahi[mt], bhi[nt]);
                    mma_bf16(acc[mt][nt], ahi[mt], blo[nt]);
                    mma_bf16(acc[mt][nt], alo[mt], bhi[nt]);
                }
        }
        __syncthreads();
    }

    // ---- epilogue ----
    const int g = lane >> 2;
    const int t2 = (lane & 3) * 2;
#pragma unroll
    for (int mt = 0; mt < MT; mt++) {
        int row0 = rowBase + wm * 64 + mt * 16 + g;
#pragma unroll
        for (int nt = 0; nt < NT; nt++) {
            int col = colBase + wn * WN + nt * 8 + t2;
            if (row0 < M)
                *(float2*)&C[(size_t)row0 * N + col] =
                    make_float2(acc[mt][nt][0], acc[mt][nt][1]);
            if (row0 + 8 < M)
                *(float2*)&C[(size_t)(row0 + 8) * N + col] =
                    make_float2(acc[mt][nt][2], acc[mt][nt][3]);
        }
    }
}

// ---------------- per-node attention dots ------------------------------------
__global__ void att_kernel(const float* __restrict__ hp1,
                           const float* __restrict__ asrc,
                           const float* __restrict__ adst,
                           float* __restrict__ a_s, float* __restrict__ a_d) {
    int warp = (blockIdx.x * blockDim.x + threadIdx.x) >> 5;
    int lane = threadIdx.x & 31;
    if (warp >= N_NODES) return;
    const float4* row = (const float4*)(hp1 + (size_t)warp * HID_);
    const float4* ws4 = (const float4*)asrc;
    const float4* wd4 = (const float4*)adst;
    float s = 0.f, d = 0.f;
#pragma unroll
    for (int i = 0; i < HID_ / 128; i++) {
        float4 v = row[lane + i * 32];
        float4 ws = ws4[lane + i * 32];
        float4 wd = wd4[lane + i * 32];
        s += v.x * ws.x + v.y * ws.y + v.z * ws.z + v.w * ws.w;
        d += v.x * wd.x + v.y * wd.y + v.z * wd.z + v.w * wd.w;
    }
#pragma unroll
    for (int o = 16; o; o >>= 1) {
        s += __shfl_xor_sync(0xffffffffu, s, o);
        d += __shfl_xor_sync(0xffffffffu, d, o);
    }
    if (lane == 0) { a_s[warp] = s; a_d[warp] = d; }
}

// ---------------- edge passes ---------------------------------------------------
__global__ void edge_logits_max(const int* __restrict__ src, const int* __restrict__ dst,
                                const float* __restrict__ a_s, const float* __restrict__ a_d,
                                float* __restrict__ ew, float* __restrict__ m) {
    int e = blockIdx.x * blockDim.x + threadIdx.x;
    if (e >= E_EDGES) return;
    int s = src[e], d = dst[e];
    float x = a_s[s] + a_d[d];
    x = x > 0.f ? x : 0.2f * x;
    ew[e] = x;
    atomicMaxFloat(&m[d], x);
}

__global__ void edge_exp_sum(const int* __restrict__ dst,
                             float* __restrict__ ew,
                             const float* __restrict__ m,
                             float* __restrict__ denom) {
    int e = blockIdx.x * blockDim.x + threadIdx.x;
    if (e >= E_EDGES) return;
    int d = dst[e];
    float ex = expf(ew[e] - m[d]);
    ew[e] = ex;
    atomicAdd(&denom[d], ex);
}

// ---------------- weighted scatter-add ------------------------------------------
__global__ void scatter_edges(const int* __restrict__ src, const int* __restrict__ dst,
                              const float* __restrict__ ew, const float* __restrict__ denom,
                              const float* __restrict__ H, float* __restrict__ out) {
    int e = (blockIdx.x * blockDim.x + threadIdx.x) >> 5;
    int lane = threadIdx.x & 31;
    if (e >= E_EDGES) return;
    int s = src[e], d = dst[e];
    float we = ew[e] / (denom[d] + 1e-16f);
    const float4* hr = (const float4*)(H + (size_t)s * HID_);
    float* orow = out + (size_t)d * HID_;
#pragma unroll
    for (int i = 0; i < HID_ / 128; i++) {
        int idx = lane + i * 32;
        float4 v = hr[idx];
        int c = idx * 4;
        atomicAdd(orow + c + 0, v.x * we);
        atomicAdd(orow + c + 1, v.y * we);
        atomicAdd(orow + c + 2, v.z * we);
        atomicAdd(orow + c + 3, v.w * we);
    }
}

// ---------------- launch ------------------------------------------------------------
extern "C" void kernel_launch(void* const* d_in, const int* in_sizes, int n_in,
                              void* d_out, int out_size) {
    const float* features = (const float*)d_in[0];  // [N, 512]
    const float* W1       = (const float*)d_in[1];  // [512, 256]
    const float* W2       = (const float*)d_in[2];  // [256, 64]
    const float* att_src  = (const float*)d_in[3];  // [256]
    const float* att_dst  = (const float*)d_in[4];  // [256]
    const int*   edge     = (const int*)d_in[5];    // [2, E]
    const int* src = edge;
    const int* dst = edge + E_EDGES;

    float* out = (float*)d_out;
    float* h2 = out;                              // [N, 64]
    float* h4 = out + (size_t)N_NODES * OUT_DIM_; // [N, 512]

    float *hp1, *h1acc, *hp3, *h3acc, *a_s, *a_d, *m, *denom, *ew;
    cudaGetSymbolAddress((void**)&hp1,   g_hp1);
    cudaGetSymbolAddress((void**)&h1acc, g_h1acc);
    cudaGetSymbolAddress((void**)&hp3,   g_hp3);
    cudaGetSymbolAddress((void**)&h3acc, g_h3acc);
    cudaGetSymbolAddress((void**)&a_s,   g_as);
    cudaGetSymbolAddress((void**)&a_d,   g_ad);
    cudaGetSymbolAddress((void**)&m,     g_m);
    cudaGetSymbolAddress((void**)&denom, g_denom);
    cudaGetSymbolAddress((void**)&ew,    g_ew);

    __nv_bfloat16 *b1hi, *b1lo, *b2hi, *b2lo, *b3hi, *b3lo, *b4hi, *b4lo;
    cudaGetSymbolAddress((void**)&b1hi, g_b1hi); cudaGetSymbolAddress((void**)&b1lo, g_b1lo);
    cudaGetSymbolAddress((void**)&b2hi, g_b2hi); cudaGetSymbolAddress((void**)&b2lo, g_b2lo);
    cudaGetSymbolAddress((void**)&b3hi, g_b3hi); cudaGetSymbolAddress((void**)&b3lo, g_b3lo);
    cudaGetSymbolAddress((void**)&b4hi, g_b4hi); cudaGetSymbolAddress((void**)&b4lo, g_b4lo);

    const int mtiles = (N_NODES + 127) / 128;  // 391

    // 0) init + weight prep
    init_bufs<<<1024, 256>>>(h1acc, h3acc, m, denom);
    prep_weights<<<(512 * 256 + 255) / 256, 256>>>(W1, W2, b1hi, b1lo, b2hi, b2lo,
                                                   b3hi, b3lo, b4hi, b4lo);

    // 1) hp1 = features @ W1
    hmma_gemm<128, false><<<dim3(2, mtiles), 256>>>(features, b1hi, b1lo, hp1,
                                                    N_NODES, HID_, IN_DIM_);
    // 2) per-node attention scores
    att_kernel<<<(N_NODES * 32 + 255) / 256, 256>>>(hp1, att_src, att_dst, a_s, a_d);
    // 3) logits + segment max
    edge_logits_max<<<(E_EDGES + 255) / 256, 256>>>(src, dst, a_s, a_d, ew, m);
    // 4) exp + segment sum
    edge_exp_sum<<<(E_EDGES + 255) / 256, 256>>>(dst, ew, m, denom);
    // 5) propagate 1
    scatter_edges<<<(E_EDGES * 32 + 255) / 256, 256>>>(src, dst, ew, denom, hp1, h1acc);
    // 6) h2 = elu(h1acc) @ W2 -> d_out
    hmma_gemm<64, true><<<dim3(1, mtiles), 256>>>(h1acc, b2hi, b2lo, h2,
                                                  N_NODES, OUT_DIM_, HID_);
    // 7) hp3 = h2 @ W2^T
    hmma_gemm<128, false><<<dim3(2, mtiles), 256>>>(h2, b3hi, b3lo, hp3,
                                                    N_NODES, HID_, OUT_DIM_);
    // 8) propagate 2 (tied attention)
    scatter_edges<<<(E_EDGES * 32 + 255) / 256, 256>>>(src, dst, ew, denom, hp3, h3acc);
    // 9) h4 = elu(h3acc) @ W1^T
    hmma_gemm<128, true><<<dim3(4, mtiles), 256>>>(h3acc, b4hi, b4lo, h4,
                                                   N_NODES, IN_DIM_, HID_);

    (void)in_sizes; (void)n_in; (void)out_size;
}

// round 4
// speedup vs baseline: 2.5715x; 1.9109x over previous
#include <cuda_runtime.h>
#include <cuda_bf16.h>
#include <math.h>
#include <stdint.h>

#define N_NODES 50000
#define E_EDGES 600000
#define IN_DIM_ 512
#define HID_ 256
#define OUT_DIM_ 64

// ---------------- scratch (static device globals; no allocations) ----------
__device__ float g_hp1[(size_t)N_NODES * HID_];    // features @ W1
__device__ float g_h1acc[(size_t)N_NODES * HID_];  // propagate 1 result
__device__ float g_hp3[(size_t)N_NODES * HID_];    // h2 @ W2^T
__device__ float g_h3acc[(size_t)N_NODES * HID_];  // propagate 2 result
__device__ float g_as[N_NODES];
__device__ float g_ad[N_NODES];

// CSR by destination
__device__ int g_deg[N_NODES];
__device__ int g_start[N_NODES];
__device__ int g_cursor[N_NODES];
__device__ int g_csr_src[E_EDGES];
__device__ float g_csr_w[E_EDGES];                 // normalized softmax weights

// prepped weight operands, B[n][k] layout (K-major rows), bf16 hi/lo split
__device__ __nv_bfloat16 g_b1hi[256 * 512], g_b1lo[256 * 512];  // W1^T view  (N=256,K=512)
__device__ __nv_bfloat16 g_b2hi[64 * 256],  g_b2lo[64 * 256];   // W2^T view  (N=64, K=256)
__device__ __nv_bfloat16 g_b3hi[256 * 64],  g_b3lo[256 * 64];   // W2 direct  (N=256,K=64)
__device__ __nv_bfloat16 g_b4hi[512 * 256], g_b4lo[512 * 256];  // W1 direct  (N=512,K=256)

// ---------------- helpers -----------------------------------------------------
__device__ __forceinline__ uint32_t smem_u32(const void* p) {
    uint32_t a;
    asm("{ .reg .u64 t; cvta.to.shared.u64 t, %1; cvt.u32.u64 %0, t; }" : "=r"(a) : "l"(p));
    return a;
}
__device__ __forceinline__ float elu_f(float x) {
    return x > 0.f ? x : (expf(x) - 1.f);
}
__device__ __forceinline__ void split_bf16(float x, __nv_bfloat16& hi, __nv_bfloat16& lo) {
    hi = __float2bfloat16_rn(x);
    lo = __float2bfloat16_rn(x - __bfloat162float(hi));
}
__device__ __forceinline__ void ldsm_x4(uint32_t addr, uint32_t* r) {
    asm volatile("ldmatrix.sync.aligned.m8n8.x4.shared.b16 {%0,%1,%2,%3}, [%4];"
                 : "=r"(r[0]), "=r"(r[1]), "=r"(r[2]), "=r"(r[3]) : "r"(addr));
}
__device__ __forceinline__ void ldsm_x2(uint32_t addr, uint32_t* r) {
    asm volatile("ldmatrix.sync.aligned.m8n8.x2.shared.b16 {%0,%1}, [%2];"
                 : "=r"(r[0]), "=r"(r[1]) : "r"(addr));
}
__device__ __forceinline__ void mma_bf16(float* d, const uint32_t* a, const uint32_t* b) {
    asm volatile(
        "mma.sync.aligned.m16n8k16.row.col.f32.bf16.bf16.f32 "
        "{%0,%1,%2,%3}, {%4,%5,%6,%7}, {%8,%9}, {%0,%1,%2,%3};"
        : "+f"(d[0]), "+f"(d[1]), "+f"(d[2]), "+f"(d[3])
        : "r"(a[0]), "r"(a[1]), "r"(a[2]), "r"(a[3]), "r"(b[0]), "r"(b[1]));
}

// ---------------- CSR build -----------------------------------------------------
__global__ void zero_deg(int* deg) {
    int i = blockIdx.x * blockDim.x + threadIdx.x;
    if (i < N_NODES) deg[i] = 0;
}

__global__ void count_deg(const int* __restrict__ dst, int* __restrict__ deg) {
    int e = blockIdx.x * blockDim.x + threadIdx.x;
    if (e < E_EDGES) atomicAdd(&deg[dst[e]], 1);
}

// single-block exclusive scan over 50000 ints (1024 threads, chunked with carry)
__global__ void scan_deg(const int* __restrict__ deg, int* __restrict__ start,
                         int* __restrict__ cursor) {
    __shared__ int warp_sums[32];
    __shared__ int s_carry;
    if (threadIdx.x == 0) s_carry = 0;
    __syncthreads();
    const int tid = threadIdx.x;
    const int lane = tid & 31;
    const int wid = tid >> 5;
    for (int base = 0; base < N_NODES; base += 1024) {
        int i = base + tid;
        int v = (i < N_NODES) ? deg[i] : 0;
        // warp inclusive scan
        int incl = v;
#pragma unroll
        for (int o = 1; o < 32; o <<= 1) {
            int t = __shfl_up_sync(0xffffffffu, incl, o);
            if (lane >= o) incl += t;
        }
        if (lane == 31) warp_sums[wid] = incl;
        __syncthreads();
        if (wid == 0) {
            int ws = warp_sums[lane];
            int wincl = ws;
#pragma unroll
            for (int o = 1; o < 32; o <<= 1) {
                int t = __shfl_up_sync(0xffffffffu, wincl, o);
                if (lane >= o) wincl += t;
            }
            warp_sums[lane] = wincl - ws;  // exclusive warp offsets
        }
        __syncthreads();
        int excl = incl - v + warp_sums[wid] + s_carry;
        if (i < N_NODES) { start[i] = excl; cursor[i] = excl; }
        __syncthreads();
        if (tid == 1023) s_carry = excl + v;
        __syncthreads();
    }
}

__global__ void fill_csr(const int* __restrict__ src, const int* __restrict__ dst,
                         int* __restrict__ cursor, int* __restrict__ csr_src) {
    int e = blockIdx.x * blockDim.x + threadIdx.x;
    if (e >= E_EDGES) return;
    int pos = atomicAdd(&cursor[dst[e]], 1);
    csr_src[pos] = src[e];
}

// ---------------- per-dst softmax over CSR edge list (warp per node) -------------
__global__ void csr_softmax(const int* __restrict__ start, const int* __restrict__ deg,
                            const int* __restrict__ csr_src,
                            const float* __restrict__ a_s, const float* __restrict__ a_d,
                            float* __restrict__ csr_w) {
    int d = (blockIdx.x * blockDim.x + threadIdx.x) >> 5;
    int lane = threadIdx.x & 31;
    if (d >= N_NODES) return;
    int s0 = start[d], n = deg[d];
    float ad = a_d[d];
    float mx = -INFINITY;
    for (int i = lane; i < n; i += 32) {
        float x = a_s[csr_src[s0 + i]] + ad;
        x = x > 0.f ? x : 0.2f * x;     // leaky_relu slope 0.2
        csr_w[s0 + i] = x;
        mx = fmaxf(mx, x);
    }
#pragma unroll
    for (int o = 16; o; o >>= 1) mx = fmaxf(mx, __shfl_xor_sync(0xffffffffu, mx, o));
    float sum = 0.f;
    for (int i = lane; i < n; i += 32) {
        float ex = expf(csr_w[s0 + i] - mx);
        csr_w[s0 + i] = ex;
        sum += ex;
    }
#pragma unroll
    for (int o = 16; o; o >>= 1) sum += __shfl_xor_sync(0xffffffffu, sum, o);
    float inv = 1.f / (sum + 1e-16f);
    for (int i = lane; i < n; i += 32) csr_w[s0 + i] *= inv;
}

// ---------------- gather propagate (warp per dst, no atomics) ---------------------
__global__ void __launch_bounds__(256)
propagate_csr(const int* __restrict__ start, const int* __restrict__ deg,
              const int* __restrict__ csr_src, const float* __restrict__ csr_w,
              const float* __restrict__ H, float* __restrict__ out) {
    int d = (blockIdx.x * blockDim.x + threadIdx.x) >> 5;
    int lane = threadIdx.x & 31;
    if (d >= N_NODES) return;
    int s0 = start[d], n = deg[d];
    float4 acc0 = make_float4(0.f, 0.f, 0.f, 0.f);
    float4 acc1 = make_float4(0.f, 0.f, 0.f, 0.f);
    int i = 0;
    for (; i + 2 <= n; i += 2) {
        int sA = csr_src[s0 + i], sB = csr_src[s0 + i + 1];
        float wA = csr_w[s0 + i], wB = csr_w[s0 + i + 1];
        const float4* rA = (const float4*)(H + (size_t)sA * HID_);
        const float4* rB = (const float4*)(H + (size_t)sB * HID_);
        float4 a0 = rA[lane], a1 = rA[lane + 32];
        float4 b0 = rB[lane], b1 = rB[lane + 32];
        acc0.x = fmaf(a0.x, wA, acc0.x); acc0.y = fmaf(a0.y, wA, acc0.y);
        acc0.z = fmaf(a0.z, wA, acc0.z); acc0.w = fmaf(a0.w, wA, acc0.w);
        acc1.x = fmaf(a1.x, wA, acc1.x); acc1.y = fmaf(a1.y, wA, acc1.y);
        acc1.z = fmaf(a1.z, wA, acc1.z); acc1.w = fmaf(a1.w, wA, acc1.w);
        acc0.x = fmaf(b0.x, wB, acc0.x); acc0.y = fmaf(b0.y, wB, acc0.y);
        acc0.z = fmaf(b0.z, wB, acc0.z); acc0.w = fmaf(b0.w, wB, acc0.w);
        acc1.x = fmaf(b1.x, wB, acc1.x); acc1.y = fmaf(b1.y, wB, acc1.y);
        acc1.z = fmaf(b1.z, wB, acc1.z); acc1.w = fmaf(b1.w, wB, acc1.w);
    }
    if (i < n) {
        int s = csr_src[s0 + i];
        float w = csr_w[s0 + i];
        const float4* r = (const float4*)(H + (size_t)s * HID_);
        float4 a0 = r[lane], a1 = r[lane + 32];
        acc0.x = fmaf(a0.x, w, acc0.x); acc0.y = fmaf(a0.y, w, acc0.y);
        acc0.z = fmaf(a0.z, w, acc0.z); acc0.w = fmaf(a0.w, w, acc0.w);
        acc1.x = fmaf(a1.x, w, acc1.x); acc1.y = fmaf(a1.y, w, acc1.y);
        acc1.z = fmaf(a1.z, w, acc1.z); acc1.w = fmaf(a1.w, w, acc1.w);
    }
    float4* orow = (float4*)(out + (size_t)d * HID_);
    orow[lane] = acc0;
    orow[lane + 32] = acc1;
}

// ---------------- weight prep: split + (transpose where needed) ------------------
__global__ void prep_weights(const float* __restrict__ W1, const float* __restrict__ W2,
                             __nv_bfloat16* b1hi, __nv_bfloat16* b1lo,
                             __nv_bfloat16* b2hi, __nv_bfloat16* b2lo,
                             __nv_bfloat16* b3hi, __nv_bfloat16* b3lo,
                             __nv_bfloat16* b4hi, __nv_bfloat16* b4lo) {
    int i = blockIdx.x * blockDim.x + threadIdx.x;
    if (i < 512 * 256) {  // W1[k][n]
        int k = i >> 8, n = i & 255;
        __nv_bfloat16 hi, lo;
        split_bf16(W1[i], hi, lo);
        b4hi[i] = hi;           b4lo[i] = lo;            // W1 direct  [512][256]
        b1hi[n * 512 + k] = hi; b1lo[n * 512 + k] = lo;  // W1^T       [256][512]
    }
    if (i < 256 * 64) {   // W2[k][n]
        int k = i >> 6, n = i & 63;
        __nv_bfloat16 hi, lo;
        split_bf16(W2[i], hi, lo);
        b3hi[i] = hi;           b3lo[i] = lo;            // W2 direct  [256][64]
        b2hi[n * 256 + k] = hi; b2lo[n * 256 + k] = lo;  // W2^T       [64][256]
    }
}

// ---------------- HMMA split-fp32 GEMM --------------------------------------------
template <int BN, bool ELUA>
__global__ void __launch_bounds__(256)
hmma_gemm(const float* __restrict__ A,
          const __nv_bfloat16* __restrict__ Bhi, const __nv_bfloat16* __restrict__ Blo,
          float* __restrict__ C, int M, int N, int K) {
    constexpr int SP = 40;              // padded row stride (bf16 elems) -> 80B
    constexpr int WN = BN / 4;
    constexpr int MT = 4;
    constexpr int NT = WN / 8;

    __shared__ __nv_bfloat16 sAhi[128 * SP];
    __shared__ __nv_bfloat16 sAlo[128 * SP];
    __shared__ __nv_bfloat16 sBhi[BN * SP];
    __shared__ __nv_bfloat16 sBlo[BN * SP];

    const int tid = threadIdx.x;
    const int wid = tid >> 5;
    const int lane = tid & 31;
    const int wm = wid >> 2;
    const int wn = wid & 3;

    const int rowBase = blockIdx.y * 128;
    const int colBase = blockIdx.x * BN;

    const uint32_t sAhi_b = smem_u32(sAhi);
    const uint32_t sAlo_b = smem_u32(sAlo);
    const uint32_t sBhi_b = smem_u32(sBhi);
    const uint32_t sBlo_b = smem_u32(sBlo);

    float acc[MT][NT][4];
#pragma unroll
    for (int i = 0; i < MT; i++)
#pragma unroll
        for (int j = 0; j < NT; j++)
#pragma unroll
            for (int c = 0; c < 4; c++) acc[i][j][c] = 0.f;

    const int aq = lane >> 3;
    const int a_row_in = (aq & 1) * 8 + (lane & 7);
    const int a_col_off = (aq >> 1) * 8;
    const int b_row_in = lane & 7;
    const int b_col_off = ((lane >> 3) & 1) * 8;

    for (int k0 = 0; k0 < K; k0 += 32) {
#pragma unroll
        for (int i = 0; i < 4; i++) {
            int u = tid + i * 256;
            int r = u >> 3;
            int q = u & 7;
            int grow = rowBase + r;
            float4 v = make_float4(0.f, 0.f, 0.f, 0.f);
            if (grow < M) v = *(const float4*)(A + (size_t)grow * K + k0 + q * 4);
            if (ELUA) {
                v.x = elu_f(v.x); v.y = elu_f(v.y);
                v.z = elu_f(v.z); v.w = elu_f(v.w);
            }
            __nv_bfloat16 hx, lx, hy, ly, hz, lz, hw, lw;
            split_bf16(v.x, hx, lx); split_bf16(v.y, hy, ly);
            split_bf16(v.z, hz, lz); split_bf16(v.w, hw, lw);
            __nv_bfloat162 h01 = __nv_bfloat162(hx, hy), h23 = __nv_bfloat162(hz, hw);
            __nv_bfloat162 l01 = __nv_bfloat162(lx, ly), l23 = __nv_bfloat162(lz, lw);
            *(uint2*)&sAhi[r * SP + q * 4] = make_uint2(*(uint32_t*)&h01, *(uint32_t*)&h23);
            *(uint2*)&sAlo[r * SP + q * 4] = make_uint2(*(uint32_t*)&l01, *(uint32_t*)&l23);
        }
#pragma unroll
        for (int i = 0; i < BN / 64; i++) {
            int u = tid + i * 256;
            int r = u >> 2;
            int q = u & 3;
            size_t gidx = (size_t)(colBase + r) * K + k0 + q * 8;
            *(uint4*)&sBhi[r * SP + q * 8] = *(const uint4*)(Bhi + gidx);
            *(uint4*)&sBlo[r * SP + q * 8] = *(const uint4*)(Blo + gidx);
        }
        __syncthreads();

#pragma unroll
        for (int ks = 0; ks < 2; ks++) {
            uint32_t ahi[MT][4], alo[MT][4];
#pragma unroll
            for (int mt = 0; mt < MT; mt++) {
                int row = wm * 64 + mt * 16 + a_row_in;
                int col = ks * 16 + a_col_off;
                uint32_t off = (uint32_t)(row * SP + col) * 2;
                ldsm_x4(sAhi_b + off, ahi[mt]);
                ldsm_x4(sAlo_b + off, alo[mt]);
            }
            uint32_t bhi[NT][2], blo[NT][2];
#pragma unroll
            for (int nt = 0; nt < NT; nt++) {
                int row = wn * WN + nt * 8 + b_row_in;
                int col = ks * 16 + b_col_off;
                uint32_t off = (uint32_t)(row * SP + col) * 2;
                ldsm_x2(sBhi_b + off, bhi[nt]);
                ldsm_x2(sBlo_b + off, blo[nt]);
            }
#pragma unroll
            for (int mt = 0; mt < MT; mt++)
#pragma unroll
                for (int nt = 0; nt < NT; nt++) {
                    mma_bf16(acc[mt][nt], ahi[mt], bhi[nt]);
                    mma_bf16(acc[mt][nt], ahi[mt], blo[nt]);
                    mma_bf16(acc[mt][nt], alo[mt], bhi[nt]);
                }
        }
        __syncthreads();
    }

    const int g = lane >> 2;
    const int t2 = (lane & 3) * 2;
#pragma unroll
    for (int mt = 0; mt < MT; mt++) {
        int row0 = rowBase + wm * 64 + mt * 16 + g;
#pragma unroll
        for (int nt = 0; nt < NT; nt++) {
            int col = colBase + wn * WN + nt * 8 + t2;
            if (row0 < M)
                *(float2*)&C[(size_t)row0 * N + col] =
                    make_float2(acc[mt][nt][0], acc[mt][nt][1]);
            if (row0 + 8 < M)
                *(float2*)&C[(size_t)(row0 + 8) * N + col] =
                    make_float2(acc[mt][nt][2], acc[mt][nt][3]);
        }
    }
}

// ---------------- per-node attention dots ------------------------------------
__global__ void att_kernel(const float* __restrict__ hp1,
                           const float* __restrict__ asrc,
                           const float* __restrict__ adst,
                           float* __restrict__ a_s, float* __restrict__ a_d) {
    int warp = (blockIdx.x * blockDim.x + threadIdx.x) >> 5;
    int lane = threadIdx.x & 31;
    if (warp >= N_NODES) return;
    const float4* row = (const float4*)(hp1 + (size_t)warp * HID_);
    const float4* ws4 = (const float4*)asrc;
    const float4* wd4 = (const float4*)adst;
    float s = 0.f, d = 0.f;
#pragma unroll
    for (int i = 0; i < HID_ / 128; i++) {
        float4 v = row[lane + i * 32];
        float4 ws = ws4[lane + i * 32];
        float4 wd = wd4[lane + i * 32];
        s += v.x * ws.x + v.y * ws.y + v.z * ws.z + v.w * ws.w;
        d += v.x * wd.x + v.y * wd.y + v.z * wd.z + v.w * wd.w;
    }
#pragma unroll
    for (int o = 16; o; o >>= 1) {
        s += __shfl_xor_sync(0xffffffffu, s, o);
        d += __shfl_xor_sync(0xffffffffu, d, o);
    }
    if (lane == 0) { a_s[warp] = s; a_d[warp] = d; }
}

// ---------------- launch ------------------------------------------------------------
extern "C" void kernel_launch(void* const* d_in, const int* in_sizes, int n_in,
                              void* d_out, int out_size) {
    const float* features = (const float*)d_in[0];  // [N, 512]
    const float* W1       = (const float*)d_in[1];  // [512, 256]
    const float* W2       = (const float*)d_in[2];  // [256, 64]
    const float* att_src  = (const float*)d_in[3];  // [256]
    const float* att_dst  = (const float*)d_in[4];  // [256]
    const int*   edge     = (const int*)d_in[5];    // [2, E]
    const int* src = edge;
    const int* dst = edge + E_EDGES;

    float* out = (float*)d_out;
    float* h2 = out;                              // [N, 64]
    float* h4 = out + (size_t)N_NODES * OUT_DIM_; // [N, 512]

    float *hp1, *h1acc, *hp3, *h3acc, *a_s, *a_d;
    cudaGetSymbolAddress((void**)&hp1,   g_hp1);
    cudaGetSymbolAddress((void**)&h1acc, g_h1acc);
    cudaGetSymbolAddress((void**)&hp3,   g_hp3);
    cudaGetSymbolAddress((void**)&h3acc, g_h3acc);
    cudaGetSymbolAddress((void**)&a_s,   g_as);
    cudaGetSymbolAddress((void**)&a_d,   g_ad);

    int *deg, *start, *cursor, *csr_src;
    float* csr_w;
    cudaGetSymbolAddress((void**)&deg,     g_deg);
    cudaGetSymbolAddress((void**)&start,   g_start);
    cudaGetSymbolAddress((void**)&cursor,  g_cursor);
    cudaGetSymbolAddress((void**)&csr_src, g_csr_src);
    cudaGetSymbolAddress((void**)&csr_w,   g_csr_w);

    __nv_bfloat16 *b1hi, *b1lo, *b2hi, *b2lo, *b3hi, *b3lo, *b4hi, *b4lo;
    cudaGetSymbolAddress((void**)&b1hi, g_b1hi); cudaGetSymbolAddress((void**)&b1lo, g_b1lo);
    cudaGetSymbolAddress((void**)&b2hi, g_b2hi); cudaGetSymbolAddress((void**)&b2lo, g_b2lo);
    cudaGetSymbolAddress((void**)&b3hi, g_b3hi); cudaGetSymbolAddress((void**)&b3lo, g_b3lo);
    cudaGetSymbolAddress((void**)&b4hi, g_b4hi); cudaGetSymbolAddress((void**)&b4lo, g_b4lo);

    const int mtiles = (N_NODES + 127) / 128;  // 391
    const int nodeWarpGrid = (N_NODES * 32 + 255) / 256;

    // --- CSR build (independent of GEMMs) ---
    zero_deg<<<(N_NODES + 255) / 256, 256>>>(deg);
    count_deg<<<(E_EDGES + 255) / 256, 256>>>(dst, deg);
    scan_deg<<<1, 1024>>>(deg, start, cursor);
    fill_csr<<<(E_EDGES + 255) / 256, 256>>>(src, dst, cursor, csr_src);

    // --- weights prep ---
    prep_weights<<<(512 * 256 + 255) / 256, 256>>>(W1, W2, b1hi, b1lo, b2hi, b2lo,
                                                   b3hi, b3lo, b4hi, b4lo);

    // 1) hp1 = features @ W1
    hmma_gemm<128, false><<<dim3(2, mtiles), 256>>>(features, b1hi, b1lo, hp1,
                                                    N_NODES, HID_, IN_DIM_);
    // 2) per-node attention scores
    att_kernel<<<nodeWarpGrid, 256>>>(hp1, att_src, att_dst, a_s, a_d);
    // 3) per-dst softmax over CSR edges
    csr_softmax<<<nodeWarpGrid, 256>>>(start, deg, csr_src, a_s, a_d, csr_w);
    // 4) propagate 1 (pure gather)
    propagate_csr<<<nodeWarpGrid, 256>>>(start, deg, csr_src, csr_w, hp1, h1acc);
    // 5) h2 = elu(h1acc) @ W2 -> d_out
    hmma_gemm<64, true><<<dim3(1, mtiles), 256>>>(h1acc, b2hi, b2lo, h2,
                                                  N_NODES, OUT_DIM_, HID_);
    // 6) hp3 = h2 @ W2^T
    hmma_gemm<128, false><<<dim3(2, mtiles), 256>>>(h2, b3hi, b3lo, hp3,
                                                    N_NODES, HID_, OUT_DIM_);
    // 7) propagate 2 (tied attention)
    propagate_csr<<<nodeWarpGrid, 256>>>(start, deg, csr_src, csr_w, hp3, h3acc);
    // 8) h4 = elu(h3acc) @ W1^T
    hmma_gemm<128, true><<<dim3(4, mtiles), 256>>>(h3acc, b4hi, b4lo, h4,
                                                   N_NODES, IN_DIM_, HID_);

    (void)in_sizes; (void)n_in; (void)out_size;
}

// round 5
// speedup vs baseline: 2.8337x; 1.1019x over previous
#include <cuda_runtime.h>
#include <cuda_bf16.h>
#include <math.h>
#include <stdint.h>

#define N_NODES 50000
#define E_EDGES 600000
#define IN_DIM_ 512
#define HID_ 256
#define OUT_DIM_ 64

// ---------------- scratch (static device globals; no allocations) ----------
__device__ float g_hp1[(size_t)N_NODES * HID_];
__device__ float g_h1acc[(size_t)N_NODES * HID_];
__device__ float g_hp3[(size_t)N_NODES * HID_];
__device__ float g_h3acc[(size_t)N_NODES * HID_];
__device__ float g_as[N_NODES];
__device__ float g_ad[N_NODES];

// CSR by destination
__device__ int g_deg[N_NODES];
__device__ int g_start[N_NODES];
__device__ int g_cursor[N_NODES];
__device__ int g_csr_src[E_EDGES];
__device__ float g_csr_w[E_EDGES];

// prepped weight operands, B[n][k] layout (K-major rows), bf16 hi/lo split
__device__ __nv_bfloat16 g_b1hi[256 * 512], g_b1lo[256 * 512];  // W1^T  (N=256,K=512)
__device__ __nv_bfloat16 g_b2hi[64 * 256],  g_b2lo[64 * 256];   // W2^T  (N=64, K=256)
__device__ __nv_bfloat16 g_b3hi[256 * 64],  g_b3lo[256 * 64];   // W2    (N=256,K=64)
__device__ __nv_bfloat16 g_b4hi[512 * 256], g_b4lo[512 * 256];  // W1    (N=512,K=256)

// ---------------- helpers -----------------------------------------------------
__device__ __forceinline__ uint32_t smem_u32(const void* p) {
    uint32_t a;
    asm("{ .reg .u64 t; cvta.to.shared.u64 t, %1; cvt.u32.u64 %0, t; }" : "=r"(a) : "l"(p));
    return a;
}
__device__ __forceinline__ float elu_f(float x) {
    return x > 0.f ? x : (expf(x) - 1.f);
}
__device__ __forceinline__ void split_bf16(float x, __nv_bfloat16& hi, __nv_bfloat16& lo) {
    hi = __float2bfloat16_rn(x);
    lo = __float2bfloat16_rn(x - __bfloat162float(hi));
}
__device__ __forceinline__ void ldsm_x4(uint32_t addr, uint32_t* r) {
    asm volatile("ldmatrix.sync.aligned.m8n8.x4.shared.b16 {%0,%1,%2,%3}, [%4];"
                 : "=r"(r[0]), "=r"(r[1]), "=r"(r[2]), "=r"(r[3]) : "r"(addr));
}
__device__ __forceinline__ void mma_bf16(float* d, const uint32_t* a, const uint32_t* b) {
    asm volatile(
        "mma.sync.aligned.m16n8k16.row.col.f32.bf16.bf16.f32 "
        "{%0,%1,%2,%3}, {%4,%5,%6,%7}, {%8,%9}, {%0,%1,%2,%3};"
        : "+f"(d[0]), "+f"(d[1]), "+f"(d[2]), "+f"(d[3])
        : "r"(a[0]), "r"(a[1]), "r"(a[2]), "r"(a[3]), "r"(b[0]), "r"(b[1]));
}

// ---------------- init / CSR build ----------------------------------------------
__global__ void zero_init(int* deg, float* a_s, float* a_d) {
    int i = blockIdx.x * blockDim.x + threadIdx.x;
    if (i < N_NODES) { deg[i] = 0; a_s[i] = 0.f; a_d[i] = 0.f; }
}

__global__ void count_deg(const int* __restrict__ dst, int* __restrict__ deg) {
    int e = blockIdx.x * blockDim.x + threadIdx.x;
    if (e < E_EDGES) atomicAdd(&deg[dst[e]], 1);
}

__global__ void scan_deg(const int* __restrict__ deg, int* __restrict__ start,
                         int* __restrict__ cursor) {
    __shared__ int warp_sums[32];
    __shared__ int s_carry;
    if (threadIdx.x == 0) s_carry = 0;
    __syncthreads();
    const int tid = threadIdx.x;
    const int lane = tid & 31;
    const int wid = tid >> 5;
    for (int base = 0; base < N_NODES; base += 1024) {
        int i = base + tid;
        int v = (i < N_NODES) ? deg[i] : 0;
        int incl = v;
#pragma unroll
        for (int o = 1; o < 32; o <<= 1) {
            int t = __shfl_up_sync(0xffffffffu, incl, o);
            if (lane >= o) incl += t;
        }
        if (lane == 31) warp_sums[wid] = incl;
        __syncthreads();
        if (wid == 0) {
            int ws = warp_sums[lane];
            int wincl = ws;
#pragma unroll
            for (int o = 1; o < 32; o <<= 1) {
                int t = __shfl_up_sync(0xffffffffu, wincl, o);
                if (lane >= o) wincl += t;
            }
            warp_sums[lane] = wincl - ws;
        }
        __syncthreads();
        int excl = incl - v + warp_sums[wid] + s_carry;
        if (i < N_NODES) { start[i] = excl; cursor[i] = excl; }
        __syncthreads();
        if (tid == 1023) s_carry = excl + v;
        __syncthreads();
    }
}

__global__ void fill_csr(const int* __restrict__ src, const int* __restrict__ dst,
                         int* __restrict__ cursor, int* __restrict__ csr_src) {
    int e = blockIdx.x * blockDim.x + threadIdx.x;
    if (e >= E_EDGES) return;
    int pos = atomicAdd(&cursor[dst[e]], 1);
    csr_src[pos] = src[e];
}

// ---------------- per-dst softmax (single pass for n<=64) ------------------------
__global__ void csr_softmax(const int* __restrict__ start, const int* __restrict__ deg,
                            const int* __restrict__ csr_src,
                            const float* __restrict__ a_s, const float* __restrict__ a_d,
                            float* __restrict__ csr_w) {
    int d = (blockIdx.x * blockDim.x + threadIdx.x) >> 5;
    int lane = threadIdx.x & 31;
    if (d >= N_NODES) return;
    int s0 = start[d], n = deg[d];
    if (n == 0) return;
    float ad = a_d[d];
    if (n <= 64) {
        float l0 = -INFINITY, l1 = -INFINITY;
        if (lane < n) {
            float x = a_s[csr_src[s0 + lane]] + ad;
            l0 = x > 0.f ? x : 0.2f * x;
        }
        if (lane + 32 < n) {
            float x = a_s[csr_src[s0 + lane + 32]] + ad;
            l1 = x > 0.f ? x : 0.2f * x;
        }
        float mx = fmaxf(l0, l1);
#pragma unroll
        for (int o = 16; o; o >>= 1) mx = fmaxf(mx, __shfl_xor_sync(0xffffffffu, mx, o));
        float e0 = (lane < n) ? expf(l0 - mx) : 0.f;
        float e1 = (lane + 32 < n) ? expf(l1 - mx) : 0.f;
        float sum = e0 + e1;
#pragma unroll
        for (int o = 16; o; o >>= 1) sum += __shfl_xor_sync(0xffffffffu, sum, o);
        float inv = 1.f / (sum + 1e-16f);
        if (lane < n) csr_w[s0 + lane] = e0 * inv;
        if (lane + 32 < n) csr_w[s0 + lane + 32] = e1 * inv;
    } else {
        // fallback (rare): 3-pass through global
        float mx = -INFINITY;
        for (int i = lane; i < n; i += 32) {
            float x = a_s[csr_src[s0 + i]] + ad;
            x = x > 0.f ? x : 0.2f * x;
            csr_w[s0 + i] = x;
            mx = fmaxf(mx, x);
        }
#pragma unroll
        for (int o = 16; o; o >>= 1) mx = fmaxf(mx, __shfl_xor_sync(0xffffffffu, mx, o));
        float sum = 0.f;
        for (int i = lane; i < n; i += 32) {
            float ex = expf(csr_w[s0 + i] - mx);
            csr_w[s0 + i] = ex;
            sum += ex;
        }
#pragma unroll
        for (int o = 16; o; o >>= 1) sum += __shfl_xor_sync(0xffffffffu, sum, o);
        float inv = 1.f / (sum + 1e-16f);
        for (int i = lane; i < n; i += 32) csr_w[s0 + i] *= inv;
    }
}

// ---------------- gather propagate (warp per dst, no atomics) ---------------------
__global__ void __launch_bounds__(256)
propagate_csr(const int* __restrict__ start, const int* __restrict__ deg,
              const int* __restrict__ csr_src, const float* __restrict__ csr_w,
              const float* __restrict__ H, float* __restrict__ out) {
    int d = (blockIdx.x * blockDim.x + threadIdx.x) >> 5;
    int lane = threadIdx.x & 31;
    if (d >= N_NODES) return;
    int s0 = start[d], n = deg[d];
    float4 acc0 = make_float4(0.f, 0.f, 0.f, 0.f);
    float4 acc1 = make_float4(0.f, 0.f, 0.f, 0.f);
    int i = 0;
    for (; i + 2 <= n; i += 2) {
        int sA = csr_src[s0 + i], sB = csr_src[s0 + i + 1];
        float wA = csr_w[s0 + i], wB = csr_w[s0 + i + 1];
        const float4* rA = (const float4*)(H + (size_t)sA * HID_);
        const float4* rB = (const float4*)(H + (size_t)sB * HID_);
        float4 a0 = rA[lane], a1 = rA[lane + 32];
        float4 b0 = rB[lane], b1 = rB[lane + 32];
        acc0.x = fmaf(a0.x, wA, acc0.x); acc0.y = fmaf(a0.y, wA, acc0.y);
        acc0.z = fmaf(a0.z, wA, acc0.z); acc0.w = fmaf(a0.w, wA, acc0.w);
        acc1.x = fmaf(a1.x, wA, acc1.x); acc1.y = fmaf(a1.y, wA, acc1.y);
        acc1.z = fmaf(a1.z, wA, acc1.z); acc1.w = fmaf(a1.w, wA, acc1.w);
        acc0.x = fmaf(b0.x, wB, acc0.x); acc0.y = fmaf(b0.y, wB, acc0.y);
        acc0.z = fmaf(b0.z, wB, acc0.z); acc0.w = fmaf(b0.w, wB, acc0.w);
        acc1.x = fmaf(b1.x, wB, acc1.x); acc1.y = fmaf(b1.y, wB, acc1.y);
        acc1.z = fmaf(b1.z, wB, acc1.z); acc1.w = fmaf(b1.w, wB, acc1.w);
    }
    if (i < n) {
        int s = csr_src[s0 + i];
        float w = csr_w[s0 + i];
        const float4* r = (const float4*)(H + (size_t)s * HID_);
        float4 a0 = r[lane], a1 = r[lane + 32];
        acc0.x = fmaf(a0.x, w, acc0.x); acc0.y = fmaf(a0.y, w, acc0.y);
        acc0.z = fmaf(a0.z, w, acc0.z); acc0.w = fmaf(a0.w, w, acc0.w);
        acc1.x = fmaf(a1.x, w, acc1.x); acc1.y = fmaf(a1.y, w, acc1.y);
        acc1.z = fmaf(a1.z, w, acc1.z); acc1.w = fmaf(a1.w, w, acc1.w);
    }
    float4* orow = (float4*)(out + (size_t)d * HID_);
    orow[lane] = acc0;
    orow[lane + 32] = acc1;
}

// ---------------- weight prep ------------------------------------------------------
__global__ void prep_weights(const float* __restrict__ W1, const float* __restrict__ W2,
                             __nv_bfloat16* b1hi, __nv_bfloat16* b1lo,
                             __nv_bfloat16* b2hi, __nv_bfloat16* b2lo,
                             __nv_bfloat16* b3hi, __nv_bfloat16* b3lo,
                             __nv_bfloat16* b4hi, __nv_bfloat16* b4lo) {
    int i = blockIdx.x * blockDim.x + threadIdx.x;
    if (i < 512 * 256) {
        int k = i >> 8, n = i & 255;
        __nv_bfloat16 hi, lo;
        split_bf16(W1[i], hi, lo);
        b4hi[i] = hi;           b4lo[i] = lo;
        b1hi[n * 512 + k] = hi; b1lo[n * 512 + k] = lo;
    }
    if (i < 256 * 64) {
        int k = i >> 6, n = i & 63;
        __nv_bfloat16 hi, lo;
        split_bf16(W2[i], hi, lo);
        b3hi[i] = hi;           b3lo[i] = lo;
        b2hi[n * 256 + k] = hi; b2lo[n * 256 + k] = lo;
    }
}

// ---------------- HMMA split-fp32 GEMM, 16-warp, double-buffered --------------------
// C[M,N] = op(A)[M,K] @ B, B prepped [N][K] bf16 hi/lo. BM=128, BK=32.
// Warp grid 4(M) x BN/32(N), warp tile 32x32. Stage pipeline: reg prefetch of tile
// t+1 overlapped with MMA on tile t; ping-pong smem.
template <int BN, bool ELUA, bool ATT>
__global__ void __launch_bounds__(BN * 4)
hmma_gemm(const float* __restrict__ A,
          const __nv_bfloat16* __restrict__ Bhi, const __nv_bfloat16* __restrict__ Blo,
          float* __restrict__ C, int M, int N, int K,
          const float* __restrict__ attS, const float* __restrict__ attD,
          float* __restrict__ a_s, float* __restrict__ a_d) {
    constexpr int THREADS = BN * 4;
    constexpr int SP = 40;                    // padded row stride, bf16 elems
    constexpr int ASZ = 128 * SP * 2;         // bytes per A array (10240)
    constexpr int BSZ = BN * SP * 2;          // bytes per B array
    constexpr int WNW = BN / 32;
    constexpr int AITER = 1024 / THREADS;     // float4 per thread for A fill
    constexpr int MT = 2, NT = 4;

    extern __shared__ char sm[];
    const uint32_t smb = smem_u32(sm);

    const int tid = threadIdx.x;
    const int wid = tid >> 5;
    const int lane = tid & 31;
    const int wm = wid / WNW;
    const int wn = wid % WNW;

    const int rowBase = blockIdx.y * 128;
    const int colBase = blockIdx.x * BN;
    const int nk = K >> 5;

    float acc[MT][NT][4];
#pragma unroll
    for (int i = 0; i < MT; i++)
#pragma unroll
        for (int j = 0; j < NT; j++)
#pragma unroll
            for (int c = 0; c < 4; c++) acc[i][j][c] = 0.f;

    // prefetch registers
    float4 aR[AITER];
    uint4 bRh, bRl;

    // fill addressing
    const int b_r = tid >> 2, b_q = tid & 3;

    // ldmatrix lane addressing
    const int aq = lane >> 3;
    const int a_row_in = (aq & 1) * 8 + (lane & 7);
    const int a_col_off = (aq >> 1) * 8;
    const int b_row_in = ((lane >> 4) & 1) * 8 + (lane & 7);
    const int b_col_off = ((lane >> 3) & 1) * 8;

    auto load_regs = [&](int t) {
#pragma unroll
        for (int i = 0; i < AITER; i++) {
            int u = tid + i * THREADS;
            int r = u >> 3, q = u & 7;
            int grow = rowBase + r;
            aR[i] = make_float4(0.f, 0.f, 0.f, 0.f);
            if (grow < M) aR[i] = *(const float4*)(A + (size_t)grow * K + t * 32 + q * 4);
        }
        size_t gidx = (size_t)(colBase + b_r) * K + t * 32 + b_q * 8;
        bRh = *(const uint4*)(Bhi + gidx);
        bRl = *(const uint4*)(Blo + gidx);
    };

    auto store_smem = [&](int s) {
        char* pAhi = sm + s * (2 * ASZ);
        char* pAlo = pAhi + ASZ;
#pragma unroll
        for (int i = 0; i < AITER; i++) {
            int u = tid + i * THREADS;
            int r = u >> 3, q = u & 7;
            float4 v = aR[i];
            if (ELUA) {
                v.x = elu_f(v.x); v.y = elu_f(v.y);
                v.z = elu_f(v.z); v.w = elu_f(v.w);
            }
            __nv_bfloat16 hx, lx, hy, ly, hz, lz, hw, lw;
            split_bf16(v.x, hx, lx); split_bf16(v.y, hy, ly);
            split_bf16(v.z, hz, lz); split_bf16(v.w, hw, lw);
            __nv_bfloat162 h01 = __nv_bfloat162(hx, hy), h23 = __nv_bfloat162(hz, hw);
            __nv_bfloat162 l01 = __nv_bfloat162(lx, ly), l23 = __nv_bfloat162(lz, lw);
            uint32_t off = (uint32_t)(r * SP + q * 4) * 2;
            *(uint2*)(pAhi + off) = make_uint2(*(uint32_t*)&h01, *(uint32_t*)&h23);
            *(uint2*)(pAlo + off) = make_uint2(*(uint32_t*)&l01, *(uint32_t*)&l23);
        }
        char* pBhi = sm + 4 * ASZ + s * (2 * BSZ);
        char* pBlo = pBhi + BSZ;
        uint32_t off = (uint32_t)(b_r * SP + b_q * 8) * 2;
        *(uint4*)(pBhi + off) = bRh;
        *(uint4*)(pBlo + off) = bRl;
    };

    auto compute = [&](int s) {
        uint32_t baseAhi = smb + s * (2 * ASZ);
        uint32_t baseAlo = baseAhi + ASZ;
        uint32_t baseBhi = smb + 4 * ASZ + s * (2 * BSZ);
        uint32_t baseBlo = baseBhi + BSZ;
#pragma unroll
        for (int ks = 0; ks < 2; ks++) {
            uint32_t ah[MT][4], al[MT][4];
#pragma unroll
            for (int mt = 0; mt < MT; mt++) {
                uint32_t off = (uint32_t)((wm * 32 + mt * 16 + a_row_in) * SP +
                                          ks * 16 + a_col_off) * 2;
                ldsm_x4(baseAhi + off, ah[mt]);
                ldsm_x4(baseAlo + off, al[mt]);
            }
            uint32_t bh[NT][2], bl[NT][2];
#pragma unroll
            for (int ntp = 0; ntp < 2; ntp++) {
                uint32_t off = (uint32_t)((wn * 32 + ntp * 16 + b_row_in) * SP +
                                          ks * 16 + b_col_off) * 2;
                uint32_t r4[4];
                ldsm_x4(baseBhi + off, r4);
                bh[ntp * 2][0] = r4[0]; bh[ntp * 2][1] = r4[1];
                bh[ntp * 2 + 1][0] = r4[2]; bh[ntp * 2 + 1][1] = r4[3];
                ldsm_x4(baseBlo + off, r4);
                bl[ntp * 2][0] = r4[0]; bl[ntp * 2][1] = r4[1];
                bl[ntp * 2 + 1][0] = r4[2]; bl[ntp * 2 + 1][1] = r4[3];
            }
#pragma unroll
            for (int mt = 0; mt < MT; mt++)
#pragma unroll
                for (int nt = 0; nt < NT; nt++) {
                    mma_bf16(acc[mt][nt], ah[mt], bh[nt]);
                    mma_bf16(acc[mt][nt], ah[mt], bl[nt]);
                    mma_bf16(acc[mt][nt], al[mt], bh[nt]);
                }
        }
    };

    // ---- pipeline ----
    load_regs(0);
    store_smem(0);
    __syncthreads();
    for (int t = 0; t < nk; t++) {
        if (t + 1 < nk) load_regs(t + 1);
        compute(t & 1);
        if (t + 1 < nk) store_smem((t + 1) & 1);
        __syncthreads();
    }

    // ---- epilogue ----
    const int g = lane >> 2;
    const int t2 = (lane & 3) * 2;
#pragma unroll
    for (int mt = 0; mt < MT; mt++) {
        int row0 = rowBase + wm * 32 + mt * 16 + g;
#pragma unroll
        for (int nt = 0; nt < NT; nt++) {
            int col = colBase + wn * 32 + nt * 8 + t2;
            if (row0 < M)
                *(float2*)&C[(size_t)row0 * N + col] =
                    make_float2(acc[mt][nt][0], acc[mt][nt][1]);
            if (row0 + 8 < M)
                *(float2*)&C[(size_t)(row0 + 8) * N + col] =
                    make_float2(acc[mt][nt][2], acc[mt][nt][3]);
        }
    }

    if (ATT) {
        // fused per-row attention partial dots: a_s[row] += hp1[row,:] . attS
#pragma unroll
        for (int mt = 0; mt < MT; mt++) {
            int row0 = rowBase + wm * 32 + mt * 16 + g;
            float sp0 = 0.f, sp1 = 0.f, dp0 = 0.f, dp1 = 0.f;
#pragma unroll
            for (int nt = 0; nt < NT; nt++) {
                int col = colBase + wn * 32 + nt * 8 + t2;
                float s0 = attS[col], s1 = attS[col + 1];
                float d0 = attD[col], d1 = attD[col + 1];
                sp0 += acc[mt][nt][0] * s0 + acc[mt][nt][1] * s1;
                sp1 += acc[mt][nt][2] * s0 + acc[mt][nt][3] * s1;
                dp0 += acc[mt][nt][0] * d0 + acc[mt][nt][1] * d1;
                dp1 += acc[mt][nt][2] * d0 + acc[mt][nt][3] * d1;
            }
#pragma unroll
            for (int o = 1; o <= 2; o <<= 1) {
                sp0 += __shfl_xor_sync(0xffffffffu, sp0, o);
                sp1 += __shfl_xor_sync(0xffffffffu, sp1, o);
                dp0 += __shfl_xor_sync(0xffffffffu, dp0, o);
                dp1 += __shfl_xor_sync(0xffffffffu, dp1, o);
            }
            if ((lane & 3) == 0) {
                if (row0 < M) {
                    atomicAdd(&a_s[row0], sp0);
                    atomicAdd(&a_d[row0], dp0);
                }
                if (row0 + 8 < M) {
                    atomicAdd(&a_s[row0 + 8], sp1);
                    atomicAdd(&a_d[row0 + 8], dp1);
                }
            }
        }
    }
}

// ---------------- launch --------------------------------------------------------------
extern "C" void kernel_launch(void* const* d_in, const int* in_sizes, int n_in,
                              void* d_out, int out_size) {
    const float* features = (const float*)d_in[0];  // [N, 512]
    const float* W1       = (const float*)d_in[1];  // [512, 256]
    const float* W2       = (const float*)d_in[2];  // [256, 64]
    const float* att_src  = (const float*)d_in[3];  // [256]
    const float* att_dst  = (const float*)d_in[4];  // [256]
    const int*   edge     = (const int*)d_in[5];    // [2, E]
    const int* src = edge;
    const int* dst = edge + E_EDGES;

    float* out = (float*)d_out;
    float* h2 = out;                              // [N, 64]
    float* h4 = out + (size_t)N_NODES * OUT_DIM_; // [N, 512]

    float *hp1, *h1acc, *hp3, *h3acc, *a_s, *a_d;
    cudaGetSymbolAddress((void**)&hp1,   g_hp1);
    cudaGetSymbolAddress((void**)&h1acc, g_h1acc);
    cudaGetSymbolAddress((void**)&hp3,   g_hp3);
    cudaGetSymbolAddress((void**)&h3acc, g_h3acc);
    cudaGetSymbolAddress((void**)&a_s,   g_as);
    cudaGetSymbolAddress((void**)&a_d,   g_ad);

    int *deg, *start, *cursor, *csr_src;
    float* csr_w;
    cudaGetSymbolAddress((void**)&deg,     g_deg);
    cudaGetSymbolAddress((void**)&start,   g_start);
    cudaGetSymbolAddress((void**)&cursor,  g_cursor);
    cudaGetSymbolAddress((void**)&csr_src, g_csr_src);
    cudaGetSymbolAddress((void**)&csr_w,   g_csr_w);

    __nv_bfloat16 *b1hi, *b1lo, *b2hi, *b2lo, *b3hi, *b3lo, *b4hi, *b4lo;
    cudaGetSymbolAddress((void**)&b1hi, g_b1hi); cudaGetSymbolAddress((void**)&b1lo, g_b1lo);
    cudaGetSymbolAddress((void**)&b2hi, g_b2hi); cudaGetSymbolAddress((void**)&b2lo, g_b2lo);
    cudaGetSymbolAddress((void**)&b3hi, g_b3hi); cudaGetSymbolAddress((void**)&b3lo, g_b3lo);
    cudaGetSymbolAddress((void**)&b4hi, g_b4hi); cudaGetSymbolAddress((void**)&b4lo, g_b4lo);

    const int smem128 = 4 * 10240 + 4 * 128 * 40 * 2;  // 81920
    const int smem64  = 4 * 10240 + 4 * 64 * 40 * 2;   // 61440
    cudaFuncSetAttribute(hmma_gemm<128, false, true>,
                         cudaFuncAttributeMaxDynamicSharedMemorySize, smem128);
    cudaFuncSetAttribute(hmma_gemm<128, false, false>,
                         cudaFuncAttributeMaxDynamicSharedMemorySize, smem128);
    cudaFuncSetAttribute(hmma_gemm<128, true, false>,
                         cudaFuncAttributeMaxDynamicSharedMemorySize, smem128);
    cudaFuncSetAttribute(hmma_gemm<64, true, false>,
                         cudaFuncAttributeMaxDynamicSharedMemorySize, smem64);

    const int mtiles = (N_NODES + 127) / 128;  // 391
    const int nodeWarpGrid = (N_NODES * 32 + 255) / 256;

    // 0) init + CSR build + weight prep
    zero_init<<<(N_NODES + 255) / 256, 256>>>(deg, a_s, a_d);
    count_deg<<<(E_EDGES + 255) / 256, 256>>>(dst, deg);
    scan_deg<<<1, 1024>>>(deg, start, cursor);
    fill_csr<<<(E_EDGES + 255) / 256, 256>>>(src, dst, cursor, csr_src);
    prep_weights<<<(512 * 256 + 255) / 256, 256>>>(W1, W2, b1hi, b1lo, b2hi, b2lo,
                                                   b3hi, b3lo, b4hi, b4lo);

    // 1) hp1 = features @ W1, with fused attention partial dots
    hmma_gemm<128, false, true><<<dim3(2, mtiles), 512, smem128>>>(
        features, b1hi, b1lo, hp1, N_NODES, HID_, IN_DIM_, att_src, att_dst, a_s, a_d);
    // 2) per-dst softmax over CSR edges
    csr_softmax<<<nodeWarpGrid, 256>>>(start, deg, csr_src, a_s, a_d, csr_w);
    // 3) propagate 1 (pure gather)
    propagate_csr<<<nodeWarpGrid, 256>>>(start, deg, csr_src, csr_w, hp1, h1acc);
    // 4) h2 = elu(h1acc) @ W2 -> d_out
    hmma_gemm<64, true, false><<<dim3(1, mtiles), 256, smem64>>>(
        h1acc, b2hi, b2lo, h2, N_NODES, OUT_DIM_, HID_, nullptr, nullptr, nullptr, nullptr);
    // 5) hp3 = h2 @ W2^T
    hmma_gemm<128, false, false><<<dim3(2, mtiles), 512, smem128>>>(
        h2, b3hi, b3lo, hp3, N_NODES, HID_, OUT_DIM_, nullptr, nullptr, nullptr, nullptr);
    // 6) propagate 2 (tied attention)
    propagate_csr<<<nodeWarpGrid, 256>>>(start, deg, csr_src, csr_w, hp3, h3acc);
    // 7) h4 = elu(h3acc) @ W1^T
    hmma_gemm<128, true, false><<<dim3(4, mtiles), 512, smem128>>>(
        h3acc, b4hi, b4lo, h4, N_NODES, IN_DIM_, HID_, nullptr, nullptr, nullptr, nullptr);

    (void)in_sizes; (void)n_in; (void)out_size;
}

// round 6
// speedup vs baseline: 3.1758x; 1.1207x over previous
#include <cuda_runtime.h>
#include <cuda_bf16.h>
#include <math.h>
#include <stdint.h>

#define N_NODES 50000
#define E_EDGES 600000
#define IN_DIM_ 512
#define HID_ 256
#define OUT_DIM_ 64

// ---------------- scratch (static device globals; no allocations) ----------
__device__ float g_hp1[(size_t)N_NODES * HID_];
__device__ float g_h1acc[(size_t)N_NODES * HID_];
__device__ float g_hp3[(size_t)N_NODES * HID_];
__device__ float g_as[N_NODES];
__device__ float g_ad[N_NODES];

// CSR by destination
__device__ int g_deg[N_NODES];
__device__ int g_start[N_NODES];
__device__ int g_cursor[N_NODES];
__device__ int g_csr_src[E_EDGES];
__device__ float g_csr_w[E_EDGES];

// prepped weight operands, B[n][k] layout (K-major rows), bf16 hi/lo split
__device__ __nv_bfloat16 g_b1hi[256 * 512], g_b1lo[256 * 512];  // W1^T  (N=256,K=512)
__device__ __nv_bfloat16 g_b2hi[64 * 256],  g_b2lo[64 * 256];   // W2^T  (N=64, K=256)
__device__ __nv_bfloat16 g_b3hi[256 * 64],  g_b3lo[256 * 64];   // W2    (N=256,K=64)
__device__ __nv_bfloat16 g_b4hi[512 * 256], g_b4lo[512 * 256];  // W1    (N=512,K=256)

// ---------------- helpers -----------------------------------------------------
__device__ __forceinline__ uint32_t smem_u32(const void* p) {
    uint32_t a;
    asm("{ .reg .u64 t; cvta.to.shared.u64 t, %1; cvt.u32.u64 %0, t; }" : "=r"(a) : "l"(p));
    return a;
}
__device__ __forceinline__ float elu_f(float x) {
    return x > 0.f ? x : (expf(x) - 1.f);
}
__device__ __forceinline__ void split_bf16(float x, __nv_bfloat16& hi, __nv_bfloat16& lo) {
    hi = __float2bfloat16_rn(x);
    lo = __float2bfloat16_rn(x - __bfloat162float(hi));
}
__device__ __forceinline__ void ldsm_x4(uint32_t addr, uint32_t* r) {
    asm volatile("ldmatrix.sync.aligned.m8n8.x4.shared.b16 {%0,%1,%2,%3}, [%4];"
                 : "=r"(r[0]), "=r"(r[1]), "=r"(r[2]), "=r"(r[3]) : "r"(addr));
}
__device__ __forceinline__ void mma_bf16(float* d, const uint32_t* a, const uint32_t* b) {
    asm volatile(
        "mma.sync.aligned.m16n8k16.row.col.f32.bf16.bf16.f32 "
        "{%0,%1,%2,%3}, {%4,%5,%6,%7}, {%8,%9}, {%0,%1,%2,%3};"
        : "+f"(d[0]), "+f"(d[1]), "+f"(d[2]), "+f"(d[3])
        : "r"(a[0]), "r"(a[1]), "r"(a[2]), "r"(a[3]), "r"(b[0]), "r"(b[1]));
}

// ---------------- CSR build ----------------------------------------------------
__global__ void zero_deg(int* deg) {
    int i = blockIdx.x * blockDim.x + threadIdx.x;
    if (i < N_NODES) deg[i] = 0;
}

__global__ void count_deg(const int* __restrict__ dst, int* __restrict__ deg) {
    int e = blockIdx.x * blockDim.x + threadIdx.x;
    if (e < E_EDGES) atomicAdd(&deg[dst[e]], 1);
}

__global__ void scan_deg(const int* __restrict__ deg, int* __restrict__ start,
                         int* __restrict__ cursor) {
    __shared__ int warp_sums[32];
    __shared__ int s_carry;
    if (threadIdx.x == 0) s_carry = 0;
    __syncthreads();
    const int tid = threadIdx.x;
    const int lane = tid & 31;
    const int wid = tid >> 5;
    for (int base = 0; base < N_NODES; base += 1024) {
        int i = base + tid;
        int v = (i < N_NODES) ? deg[i] : 0;
        int incl = v;
#pragma unroll
        for (int o = 1; o < 32; o <<= 1) {
            int t = __shfl_up_sync(0xffffffffu, incl, o);
            if (lane >= o) incl += t;
        }
        if (lane == 31) warp_sums[wid] = incl;
        __syncthreads();
        if (wid == 0) {
            int ws = warp_sums[lane];
            int wincl = ws;
#pragma unroll
            for (int o = 1; o < 32; o <<= 1) {
                int t = __shfl_up_sync(0xffffffffu, wincl, o);
                if (lane >= o) wincl += t;
            }
            warp_sums[lane] = wincl - ws;
        }
        __syncthreads();
        int excl = incl - v + warp_sums[wid] + s_carry;
        if (i < N_NODES) { start[i] = excl; cursor[i] = excl; }
        __syncthreads();
        if (tid == 1023) s_carry = excl + v;
        __syncthreads();
    }
}

__global__ void fill_csr(const int* __restrict__ src, const int* __restrict__ dst,
                         int* __restrict__ cursor, int* __restrict__ csr_src) {
    int e = blockIdx.x * blockDim.x + threadIdx.x;
    if (e >= E_EDGES) return;
    int pos = atomicAdd(&cursor[dst[e]], 1);
    csr_src[pos] = src[e];
}

// ---------------- fused softmax + propagate-1 (warp per dst) --------------------
__global__ void __launch_bounds__(256)
softmax_prop(const int* __restrict__ start, const int* __restrict__ deg,
             const int* __restrict__ csr_src,
             const float* __restrict__ a_s, const float* __restrict__ a_d,
             float* __restrict__ csr_w,
             const float* __restrict__ H, float* __restrict__ out) {
    int d = (blockIdx.x * blockDim.x + threadIdx.x) >> 5;
    int lane = threadIdx.x & 31;
    if (d >= N_NODES) return;
    int s0 = start[d], n = deg[d];

    float4 acc0 = make_float4(0.f, 0.f, 0.f, 0.f);
    float4 acc1 = make_float4(0.f, 0.f, 0.f, 0.f);

    if (n > 0 && n <= 64) {
        float ad = a_d[d];
        int se0 = 0, se1 = 0;
        float l0 = -INFINITY, l1 = -INFINITY;
        if (lane < n) {
            se0 = csr_src[s0 + lane];
            float x = a_s[se0] + ad;
            l0 = x > 0.f ? x : 0.2f * x;
        }
        if (lane + 32 < n) {
            se1 = csr_src[s0 + lane + 32];
            float x = a_s[se1] + ad;
            l1 = x > 0.f ? x : 0.2f * x;
        }
        float mx = fmaxf(l0, l1);
#pragma unroll
        for (int o = 16; o; o >>= 1) mx = fmaxf(mx, __shfl_xor_sync(0xffffffffu, mx, o));
        float w0 = (lane < n) ? expf(l0 - mx) : 0.f;
        float w1 = (lane + 32 < n) ? expf(l1 - mx) : 0.f;
        float sum = w0 + w1;
#pragma unroll
        for (int o = 16; o; o >>= 1) sum += __shfl_xor_sync(0xffffffffu, sum, o);
        float inv = 1.f / (sum + 1e-16f);
        w0 *= inv; w1 *= inv;
        if (lane < n) csr_w[s0 + lane] = w0;          // reused by propagate-2
        if (lane + 32 < n) csr_w[s0 + lane + 32] = w1;

        // gather with weights broadcast from registers
        for (int i = 0; i < n; i++) {
            int si; float wi;
            if (i < 32) {
                si = __shfl_sync(0xffffffffu, se0, i);
                wi = __shfl_sync(0xffffffffu, w0, i);
            } else {
                si = __shfl_sync(0xffffffffu, se1, i - 32);
                wi = __shfl_sync(0xffffffffu, w1, i - 32);
            }
            const float4* r = (const float4*)(H + (size_t)si * HID_);
            float4 v0 = r[lane], v1 = r[lane + 32];
            acc0.x = fmaf(v0.x, wi, acc0.x); acc0.y = fmaf(v0.y, wi, acc0.y);
            acc0.z = fmaf(v0.z, wi, acc0.z); acc0.w = fmaf(v0.w, wi, acc0.w);
            acc1.x = fmaf(v1.x, wi, acc1.x); acc1.y = fmaf(v1.y, wi, acc1.y);
            acc1.z = fmaf(v1.z, wi, acc1.z); acc1.w = fmaf(v1.w, wi, acc1.w);
        }
    } else if (n > 64) {
        float ad = a_d[d];
        float mx = -INFINITY;
        for (int i = lane; i < n; i += 32) {
            float x = a_s[csr_src[s0 + i]] + ad;
            x = x > 0.f ? x : 0.2f * x;
            csr_w[s0 + i] = x;
            mx = fmaxf(mx, x);
        }
#pragma unroll
        for (int o = 16; o; o >>= 1) mx = fmaxf(mx, __shfl_xor_sync(0xffffffffu, mx, o));
        float sum = 0.f;
        for (int i = lane; i < n; i += 32) {
            float ex = expf(csr_w[s0 + i] - mx);
            csr_w[s0 + i] = ex;
            sum += ex;
        }
#pragma unroll
        for (int o = 16; o; o >>= 1) sum += __shfl_xor_sync(0xffffffffu, sum, o);
        float inv = 1.f / (sum + 1e-16f);
        for (int i = lane; i < n; i += 32) csr_w[s0 + i] *= inv;
        __threadfence_block();
        __syncwarp();
        for (int i = 0; i < n; i++) {
            int si = csr_src[s0 + i];
            float wi = csr_w[s0 + i];
            const float4* r = (const float4*)(H + (size_t)si * HID_);
            float4 v0 = r[lane], v1 = r[lane + 32];
            acc0.x = fmaf(v0.x, wi, acc0.x); acc0.y = fmaf(v0.y, wi, acc0.y);
            acc0.z = fmaf(v0.z, wi, acc0.z); acc0.w = fmaf(v0.w, wi, acc0.w);
            acc1.x = fmaf(v1.x, wi, acc1.x); acc1.y = fmaf(v1.y, wi, acc1.y);
            acc1.z = fmaf(v1.z, wi, acc1.z); acc1.w = fmaf(v1.w, wi, acc1.w);
        }
    }
    float4* orow = (float4*)(out + (size_t)d * HID_);
    orow[lane] = acc0;
    orow[lane + 32] = acc1;
}

// ---------------- propagate-2 (reads stored csr_w) --------------------------------
__global__ void __launch_bounds__(256)
propagate_csr(const int* __restrict__ start, const int* __restrict__ deg,
              const int* __restrict__ csr_src, const float* __restrict__ csr_w,
              const float* __restrict__ H, float* __restrict__ out) {
    int d = (blockIdx.x * blockDim.x + threadIdx.x) >> 5;
    int lane = threadIdx.x & 31;
    if (d >= N_NODES) return;
    int s0 = start[d], n = deg[d];
    float4 acc0 = make_float4(0.f, 0.f, 0.f, 0.f);
    float4 acc1 = make_float4(0.f, 0.f, 0.f, 0.f);
    int i = 0;
    for (; i + 2 <= n; i += 2) {
        int sA = csr_src[s0 + i], sB = csr_src[s0 + i + 1];
        float wA = csr_w[s0 + i], wB = csr_w[s0 + i + 1];
        const float4* rA = (const float4*)(H + (size_t)sA * HID_);
        const float4* rB = (const float4*)(H + (size_t)sB * HID_);
        float4 a0 = rA[lane], a1 = rA[lane + 32];
        float4 b0 = rB[lane], b1 = rB[lane + 32];
        acc0.x = fmaf(a0.x, wA, acc0.x); acc0.y = fmaf(a0.y, wA, acc0.y);
        acc0.z = fmaf(a0.z, wA, acc0.z); acc0.w = fmaf(a0.w, wA, acc0.w);
        acc1.x = fmaf(a1.x, wA, acc1.x); acc1.y = fmaf(a1.y, wA, acc1.y);
        acc1.z = fmaf(a1.z, wA, acc1.z); acc1.w = fmaf(a1.w, wA, acc1.w);
        acc0.x = fmaf(b0.x, wB, acc0.x); acc0.y = fmaf(b0.y, wB, acc0.y);
        acc0.z = fmaf(b0.z, wB, acc0.z); acc0.w = fmaf(b0.w, wB, acc0.w);
        acc1.x = fmaf(b1.x, wB, acc1.x); acc1.y = fmaf(b1.y, wB, acc1.y);
        acc1.z = fmaf(b1.z, wB, acc1.z); acc1.w = fmaf(b1.w, wB, acc1.w);
    }
    if (i < n) {
        int s = csr_src[s0 + i];
        float w = csr_w[s0 + i];
        const float4* r = (const float4*)(H + (size_t)s * HID_);
        float4 a0 = r[lane], a1 = r[lane + 32];
        acc0.x = fmaf(a0.x, w, acc0.x); acc0.y = fmaf(a0.y, w, acc0.y);
        acc0.z = fmaf(a0.z, w, acc0.z); acc0.w = fmaf(a0.w, w, acc0.w);
        acc1.x = fmaf(a1.x, w, acc1.x); acc1.y = fmaf(a1.y, w, acc1.y);
        acc1.z = fmaf(a1.z, w, acc1.z); acc1.w = fmaf(a1.w, w, acc1.w);
    }
    float4* orow = (float4*)(out + (size_t)d * HID_);
    orow[lane] = acc0;
    orow[lane + 32] = acc1;
}

// ---------------- weight prep (+ zero a_s/a_d) --------------------------------------
__global__ void prep_weights(const float* __restrict__ W1, const float* __restrict__ W2,
                             __nv_bfloat16* b1hi, __nv_bfloat16* b1lo,
                             __nv_bfloat16* b2hi, __nv_bfloat16* b2lo,
                             __nv_bfloat16* b3hi, __nv_bfloat16* b3lo,
                             __nv_bfloat16* b4hi, __nv_bfloat16* b4lo,
                             float* a_s, float* a_d) {
    int i = blockIdx.x * blockDim.x + threadIdx.x;
    if (i < N_NODES) { a_s[i] = 0.f; a_d[i] = 0.f; }
    if (i < 512 * 256) {
        int k = i >> 8, n = i & 255;
        __nv_bfloat16 hi, lo;
        split_bf16(W1[i], hi, lo);
        b4hi[i] = hi;           b4lo[i] = lo;
        b1hi[n * 512 + k] = hi; b1lo[n * 512 + k] = lo;
    }
    if (i < 256 * 64) {
        int k = i >> 6, n = i & 63;
        __nv_bfloat16 hi, lo;
        split_bf16(W2[i], hi, lo);
        b3hi[i] = hi;           b3lo[i] = lo;
        b2hi[n * 256 + k] = hi; b2lo[n * 256 + k] = lo;
    }
}

// ---------------- HMMA split-fp32 GEMM, 16-warp, double-buffered --------------------
template <int BN, bool ELUA, bool ATT>
__global__ void __launch_bounds__(BN * 4)
hmma_gemm(const float* __restrict__ A,
          const __nv_bfloat16* __restrict__ Bhi, const __nv_bfloat16* __restrict__ Blo,
          float* __restrict__ C, int M, int N, int K,
          const float* __restrict__ attS, const float* __restrict__ attD,
          float* __restrict__ a_s, float* __restrict__ a_d) {
    constexpr int THREADS = BN * 4;
    constexpr int SP = 40;
    constexpr int ASZ = 128 * SP * 2;
    constexpr int BSZ = BN * SP * 2;
    constexpr int WNW = BN / 32;
    constexpr int AITER = 1024 / THREADS;
    constexpr int MT = 2, NT = 4;

    extern __shared__ char sm[];
    const uint32_t smb = smem_u32(sm);

    const int tid = threadIdx.x;
    const int wid = tid >> 5;
    const int lane = tid & 31;
    const int wm = wid / WNW;
    const int wn = wid % WNW;

    const int rowBase = blockIdx.y * 128;
    const int colBase = blockIdx.x * BN;
    const int nk = K >> 5;

    float acc[MT][NT][4];
#pragma unroll
    for (int i = 0; i < MT; i++)
#pragma unroll
        for (int j = 0; j < NT; j++)
#pragma unroll
            for (int c = 0; c < 4; c++) acc[i][j][c] = 0.f;

    float4 aR[AITER];
    uint4 bRh, bRl;
    const int b_r = tid >> 2, b_q = tid & 3;

    const int aq = lane >> 3;
    const int a_row_in = (aq & 1) * 8 + (lane & 7);
    const int a_col_off = (aq >> 1) * 8;
    const int b_row_in = ((lane >> 4) & 1) * 8 + (lane & 7);
    const int b_col_off = ((lane >> 3) & 1) * 8;

    auto load_regs = [&](int t) {
#pragma unroll
        for (int i = 0; i < AITER; i++) {
            int u = tid + i * THREADS;
            int r = u >> 3, q = u & 7;
            int grow = rowBase + r;
            aR[i] = make_float4(0.f, 0.f, 0.f, 0.f);
            if (grow < M) aR[i] = *(const float4*)(A + (size_t)grow * K + t * 32 + q * 4);
        }
        size_t gidx = (size_t)(colBase + b_r) * K + t * 32 + b_q * 8;
        bRh = *(const uint4*)(Bhi + gidx);
        bRl = *(const uint4*)(Blo + gidx);
    };

    auto store_smem = [&](int s) {
        char* pAhi = sm + s * (2 * ASZ);
        char* pAlo = pAhi + ASZ;
#pragma unroll
        for (int i = 0; i < AITER; i++) {
            int u = tid + i * THREADS;
            int r = u >> 3, q = u & 7;
            float4 v = aR[i];
            if (ELUA) {
                v.x = elu_f(v.x); v.y = elu_f(v.y);
                v.z = elu_f(v.z); v.w = elu_f(v.w);
            }
            __nv_bfloat16 hx, lx, hy, ly, hz, lz, hw, lw;
            split_bf16(v.x, hx, lx); split_bf16(v.y, hy, ly);
            split_bf16(v.z, hz, lz); split_bf16(v.w, hw, lw);
            __nv_bfloat162 h01 = __nv_bfloat162(hx, hy), h23 = __nv_bfloat162(hz, hw);
            __nv_bfloat162 l01 = __nv_bfloat162(lx, ly), l23 = __nv_bfloat162(lz, lw);
            uint32_t off = (uint32_t)(r * SP + q * 4) * 2;
            *(uint2*)(pAhi + off) = make_uint2(*(uint32_t*)&h01, *(uint32_t*)&h23);
            *(uint2*)(pAlo + off) = make_uint2(*(uint32_t*)&l01, *(uint32_t*)&l23);
        }
        char* pBhi = sm + 4 * ASZ + s * (2 * BSZ);
        char* pBlo = pBhi + BSZ;
        uint32_t off = (uint32_t)(b_r * SP + b_q * 8) * 2;
        *(uint4*)(pBhi + off) = bRh;
        *(uint4*)(pBlo + off) = bRl;
    };

    auto compute = [&](int s) {
        uint32_t baseAhi = smb + s * (2 * ASZ);
        uint32_t baseAlo = baseAhi + ASZ;
        uint32_t baseBhi = smb + 4 * ASZ + s * (2 * BSZ);
        uint32_t baseBlo = baseBhi + BSZ;
#pragma unroll
        for (int ks = 0; ks < 2; ks++) {
            uint32_t ah[MT][4], al[MT][4];
#pragma unroll
            for (int mt = 0; mt < MT; mt++) {
                uint32_t off = (uint32_t)((wm * 32 + mt * 16 + a_row_in) * SP +
                                          ks * 16 + a_col_off) * 2;
                ldsm_x4(baseAhi + off, ah[mt]);
                ldsm_x4(baseAlo + off, al[mt]);
            }
            uint32_t bh[NT][2], bl[NT][2];
#pragma unroll
            for (int ntp = 0; ntp < 2; ntp++) {
                uint32_t off = (uint32_t)((wn * 32 + ntp * 16 + b_row_in) * SP +
                                          ks * 16 + b_col_off) * 2;
                uint32_t r4[4];
                ldsm_x4(baseBhi + off, r4);
                bh[ntp * 2][0] = r4[0]; bh[ntp * 2][1] = r4[1];
                bh[ntp * 2 + 1][0] = r4[2]; bh[ntp * 2 + 1][1] = r4[3];
                ldsm_x4(baseBlo + off, r4);
                bl[ntp * 2][0] = r4[0]; bl[ntp * 2][1] = r4[1];
                bl[ntp * 2 + 1][0] = r4[2]; bl[ntp * 2 + 1][1] = r4[3];
            }
#pragma unroll
            for (int mt = 0; mt < MT; mt++)
#pragma unroll
                for (int nt = 0; nt < NT; nt++) {
                    mma_bf16(acc[mt][nt], ah[mt], bh[nt]);
                    mma_bf16(acc[mt][nt], ah[mt], bl[nt]);
                    mma_bf16(acc[mt][nt], al[mt], bh[nt]);
                }
        }
    };

    load_regs(0);
    store_smem(0);
    __syncthreads();
    for (int t = 0; t < nk; t++) {
        if (t + 1 < nk) load_regs(t + 1);
        compute(t & 1);
        if (t + 1 < nk) store_smem((t + 1) & 1);
        __syncthreads();
    }

    const int g = lane >> 2;
    const int t2 = (lane & 3) * 2;
#pragma unroll
    for (int mt = 0; mt < MT; mt++) {
        int row0 = rowBase + wm * 32 + mt * 16 + g;
#pragma unroll
        for (int nt = 0; nt < NT; nt++) {
            int col = colBase + wn * 32 + nt * 8 + t2;
            if (row0 < M)
                *(float2*)&C[(size_t)row0 * N + col] =
                    make_float2(acc[mt][nt][0], acc[mt][nt][1]);
            if (row0 + 8 < M)
                *(float2*)&C[(size_t)(row0 + 8) * N + col] =
                    make_float2(acc[mt][nt][2], acc[mt][nt][3]);
        }
    }

    if (ATT) {
#pragma unroll
        for (int mt = 0; mt < MT; mt++) {
            int row0 = rowBase + wm * 32 + mt * 16 + g;
            float sp0 = 0.f, sp1 = 0.f, dp0 = 0.f, dp1 = 0.f;
#pragma unroll
            for (int nt = 0; nt < NT; nt++) {
                int col = colBase + wn * 32 + nt * 8 + t2;
                float s0 = attS[col], s1 = attS[col + 1];
                float d0 = attD[col], d1 = attD[col + 1];
                sp0 += acc[mt][nt][0] * s0 + acc[mt][nt][1] * s1;
                sp1 += acc[mt][nt][2] * s0 + acc[mt][nt][3] * s1;
                dp0 += acc[mt][nt][0] * d0 + acc[mt][nt][1] * d1;
                dp1 += acc[mt][nt][2] * d0 + acc[mt][nt][3] * d1;
            }
#pragma unroll
            for (int o = 1; o <= 2; o <<= 1) {
                sp0 += __shfl_xor_sync(0xffffffffu, sp0, o);
                sp1 += __shfl_xor_sync(0xffffffffu, sp1, o);
                dp0 += __shfl_xor_sync(0xffffffffu, dp0, o);
                dp1 += __shfl_xor_sync(0xffffffffu, dp1, o);
            }
            if ((lane & 3) == 0) {
                if (row0 < M) {
                    atomicAdd(&a_s[row0], sp0);
                    atomicAdd(&a_d[row0], dp0);
                }
                if (row0 + 8 < M) {
                    atomicAdd(&a_s[row0 + 8], sp1);
                    atomicAdd(&a_d[row0 + 8], dp1);
                }
            }
        }
    }
}

// ---------------- fused GEMM2 + GEMM3 ------------------------------------------------
// stage 1: h2 = elu(h1acc) @ B2  (N=64, K=256), written to gmem + split into smem
// stage 2: hp3 = h2 @ B3        (N=256, K=64, fully smem-resident)
__global__ void __launch_bounds__(512)
gemm23_fused(const float* __restrict__ A,
             const __nv_bfloat16* __restrict__ B2hi, const __nv_bfloat16* __restrict__ B2lo,
             const __nv_bfloat16* __restrict__ B3hi, const __nv_bfloat16* __restrict__ B3lo,
             float* __restrict__ H2, float* __restrict__ HP3, int M) {
    constexpr int SP = 40;                 // stage-1 row stride (bf16)
    constexpr int SP2 = 72;                // stage-2 row stride (bf16)
    constexpr int ASZ = 128 * SP * 2;      // 10240
    constexpr int BSZ = 64 * SP * 2;       // 5120
    constexpr int HSZ = 128 * SP2 * 2;     // 18432
    constexpr int B3SZ = 256 * SP2 * 2;    // 36864
    // stage1: sA[2 stages][hi,lo] @ [0, 4*ASZ) ; sB2[2][hi,lo] @ [4*ASZ, 4*ASZ+4*BSZ)
    // stage2: sHhi @0, sHlo @HSZ, sB3hi @2*HSZ, sB3lo @2*HSZ+B3SZ   (reused region)

    extern __shared__ char sm[];
    const uint32_t smb = smem_u32(sm);

    const int tid = threadIdx.x;
    const int wid = tid >> 5;
    const int lane = tid & 31;
    const int rowBase = blockIdx.y * 128;

    const int aq = lane >> 3;
    const int a_row_in = (aq & 1) * 8 + (lane & 7);
    const int a_col_off = (aq >> 1) * 8;
    const int b_row_in = ((lane >> 4) & 1) * 8 + (lane & 7);
    const int b_col_off = ((lane >> 3) & 1) * 8;
    const int g = lane >> 2;
    const int t2 = (lane & 3) * 2;

    // ---------------- stage 1: 128x64 = elu(A[128x256]) @ B2 ----------------
    {
        const int wm = wid >> 2;   // 0..3 (32 rows each)
        const int wn = wid & 3;    // 0..3 (16 cols each)
        float acc1[2][2][4];
#pragma unroll
        for (int i = 0; i < 2; i++)
#pragma unroll
            for (int j = 0; j < 2; j++)
#pragma unroll
                for (int c = 0; c < 4; c++) acc1[i][j][c] = 0.f;

        float4 aR[2];
        uint4 bRh, bRl;
        const int b_r = tid >> 2, b_q = tid & 3;  // valid for tid<256

        auto load1 = [&](int t) {
#pragma unroll
            for (int i = 0; i < 2; i++) {
                int u = tid + i * 512;
                int r = u >> 3, q = u & 7;
                int grow = rowBase + r;
                aR[i] = make_float4(0.f, 0.f, 0.f, 0.f);
                if (grow < M) aR[i] = *(const float4*)(A + (size_t)grow * 256 + t * 32 + q * 4);
            }
            if (tid < 256) {
                size_t gidx = (size_t)b_r * 256 + t * 32 + b_q * 8;
                bRh = *(const uint4*)(B2hi + gidx);
                bRl = *(const uint4*)(B2lo + gidx);
            }
        };
        auto store1 = [&](int s) {
            char* pAhi = sm + s * (2 * ASZ);
            char* pAlo = pAhi + ASZ;
#pragma unroll
            for (int i = 0; i < 2; i++) {
                int u = tid + i * 512;
                int r = u >> 3, q = u & 7;
                float4 v = aR[i];
                v.x = elu_f(v.x); v.y = elu_f(v.y);
                v.z = elu_f(v.z); v.w = elu_f(v.w);
                __nv_bfloat16 hx, lx, hy, ly, hz, lz, hw, lw;
                split_bf16(v.x, hx, lx); split_bf16(v.y, hy, ly);
                split_bf16(v.z, hz, lz); split_bf16(v.w, hw, lw);
                __nv_bfloat162 h01 = __nv_bfloat162(hx, hy), h23 = __nv_bfloat162(hz, hw);
                __nv_bfloat162 l01 = __nv_bfloat162(lx, ly), l23 = __nv_bfloat162(lz, lw);
                uint32_t off = (uint32_t)(r * SP + q * 4) * 2;
                *(uint2*)(pAhi + off) = make_uint2(*(uint32_t*)&h01, *(uint32_t*)&h23);
                *(uint2*)(pAlo + off) = make_uint2(*(uint32_t*)&l01, *(uint32_t*)&l23);
            }
            if (tid < 256) {
                char* pBhi = sm + 4 * ASZ + s * (2 * BSZ);
                char* pBlo = pBhi + BSZ;
                uint32_t off = (uint32_t)(b_r * SP + b_q * 8) * 2;
                *(uint4*)(pBhi + off) = bRh;
                *(uint4*)(pBlo + off) = bRl;
            }
        };
        auto compute1 = [&](int s) {
            uint32_t baseAhi = smb + s * (2 * ASZ);
            uint32_t baseAlo = baseAhi + ASZ;
            uint32_t baseBhi = smb + 4 * ASZ + s * (2 * BSZ);
            uint32_t baseBlo = baseBhi + BSZ;
#pragma unroll
            for (int ks = 0; ks < 2; ks++) {
                uint32_t ah[2][4], al[2][4];
#pragma unroll
                for (int mt = 0; mt < 2; mt++) {
                    uint32_t off = (uint32_t)((wm * 32 + mt * 16 + a_row_in) * SP +
                                              ks * 16 + a_col_off) * 2;
                    ldsm_x4(baseAhi + off, ah[mt]);
                    ldsm_x4(baseAlo + off, al[mt]);
                }
                uint32_t bh[2][2], bl[2][2];
                {
                    uint32_t off = (uint32_t)((wn * 16 + b_row_in) * SP +
                                              ks * 16 + b_col_off) * 2;
                    uint32_t r4[4];
                    ldsm_x4(baseBhi + off, r4);
                    bh[0][0] = r4[0]; bh[0][1] = r4[1];
                    bh[1][0] = r4[2]; bh[1][1] = r4[3];
                    ldsm_x4(baseBlo + off, r4);
                    bl[0][0] = r4[0]; bl[0][1] = r4[1];
                    bl[1][0] = r4[2]; bl[1][1] = r4[3];
                }
#pragma unroll
                for (int mt = 0; mt < 2; mt++)
#pragma unroll
                    for (int nt = 0; nt < 2; nt++) {
                        mma_bf16(acc1[mt][nt], ah[mt], bh[nt]);
                        mma_bf16(acc1[mt][nt], ah[mt], bl[nt]);
                        mma_bf16(acc1[mt][nt], al[mt], bh[nt]);
                    }
            }
        };

        load1(0);
        store1(0);
        __syncthreads();
        for (int t = 0; t < 8; t++) {
            if (t + 1 < 8) load1(t + 1);
            compute1(t & 1);
            if (t + 1 < 8) store1((t + 1) & 1);
            __syncthreads();
        }

        // epilogue 1: write h2 to gmem + split into sH (stage-2 A operand)
        char* sHhi = sm;
        char* sHlo = sm + HSZ;
#pragma unroll
        for (int mt = 0; mt < 2; mt++) {
            int rl0 = wm * 32 + mt * 16 + g;        // local rows rl0, rl0+8
#pragma unroll
            for (int nt = 0; nt < 2; nt++) {
                int col = wn * 16 + nt * 8 + t2;
                float v0 = acc1[mt][nt][0], v1 = acc1[mt][nt][1];
                float v2 = acc1[mt][nt][2], v3 = acc1[mt][nt][3];
                int grow0 = rowBase + rl0;
                if (grow0 < M) *(float2*)&H2[(size_t)grow0 * 64 + col] = make_float2(v0, v1);
                if (grow0 + 8 < M) *(float2*)&H2[(size_t)(grow0 + 8) * 64 + col] = make_float2(v2, v3);
                __nv_bfloat16 h0, l0, h1, l1, h2b, l2, h3, l3;
                split_bf16(v0, h0, l0); split_bf16(v1, h1, l1);
                split_bf16(v2, h2b, l2); split_bf16(v3, h3, l3);
                __nv_bfloat162 ha = __nv_bfloat162(h0, h1), la = __nv_bfloat162(l0, l1);
                __nv_bfloat162 hb = __nv_bfloat162(h2b, h3), lb = __nv_bfloat162(l2, l3);
                *(uint32_t*)(sHhi + (rl0 * SP2 + col) * 2) = *(uint32_t*)&ha;
                *(uint32_t*)(sHlo + (rl0 * SP2 + col) * 2) = *(uint32_t*)&la;
                *(uint32_t*)(sHhi + ((rl0 + 8) * SP2 + col) * 2) = *(uint32_t*)&hb;
                *(uint32_t*)(sHlo + ((rl0 + 8) * SP2 + col) * 2) = *(uint32_t*)&lb;
            }
        }
    }
    __syncthreads();

    // ---------------- stage 2: 128x256 = h2[128x64] @ B3 ----------------
    {
        char* sB3hi = sm + 2 * HSZ;
        char* sB3lo = sB3hi + B3SZ;
        // fill B3: 256 rows x 64 K, 8 uint4 per row per array
#pragma unroll
        for (int i = 0; i < 4; i++) {
            int u = tid + i * 512;
            int r = u >> 3, q = u & 7;
            uint32_t off = (uint32_t)(r * SP2 + q * 8) * 2;
            *(uint4*)(sB3hi + off) = *(const uint4*)(B3hi + r * 64 + q * 8);
            *(uint4*)(sB3lo + off) = *(const uint4*)(B3lo + r * 64 + q * 8);
        }
        __syncthreads();

        const int wm = wid >> 3;   // 0..1 (64 rows each)
        const int wn = wid & 7;    // 0..7 (32 cols each)
        float acc2[4][4][4];
#pragma unroll
        for (int i = 0; i < 4; i++)
#pragma unroll
            for (int j = 0; j < 4; j++)
#pragma unroll
                for (int c = 0; c < 4; c++) acc2[i][j][c] = 0.f;

        uint32_t baseHhi = smb;
        uint32_t baseHlo = smb + HSZ;
        uint32_t baseB3hi = smb + 2 * HSZ;
        uint32_t baseB3lo = baseB3hi + B3SZ;
#pragma unroll
        for (int ks = 0; ks < 4; ks++) {
            uint32_t ah[4][4], al[4][4];
#pragma unroll
            for (int mt = 0; mt < 4; mt++) {
                uint32_t off = (uint32_t)((wm * 64 + mt * 16 + a_row_in) * SP2 +
                                          ks * 16 + a_col_off) * 2;
                ldsm_x4(baseHhi + off, ah[mt]);
                ldsm_x4(baseHlo + off, al[mt]);
            }
            uint32_t bh[4][2], bl[4][2];
#pragma unroll
            for (int ntp = 0; ntp < 2; ntp++) {
                uint32_t off = (uint32_t)((wn * 32 + ntp * 16 + b_row_in) * SP2 +
                                          ks * 16 + b_col_off) * 2;
                uint32_t r4[4];
                ldsm_x4(baseB3hi + off, r4);
                bh[ntp * 2][0] = r4[0]; bh[ntp * 2][1] = r4[1];
                bh[ntp * 2 + 1][0] = r4[2]; bh[ntp * 2 + 1][1] = r4[3];
                ldsm_x4(baseB3lo + off, r4);
                bl[ntp * 2][0] = r4[0]; bl[ntp * 2][1] = r4[1];
                bl[ntp * 2 + 1][0] = r4[2]; bl[ntp * 2 + 1][1] = r4[3];
            }
#pragma unroll
            for (int mt = 0; mt < 4; mt++)
#pragma unroll
                for (int nt = 0; nt < 4; nt++) {
                    mma_bf16(acc2[mt][nt], ah[mt], bh[nt]);
                    mma_bf16(acc2[mt][nt], ah[mt], bl[nt]);
                    mma_bf16(acc2[mt][nt], al[mt], bh[nt]);
                }
        }

#pragma unroll
        for (int mt = 0; mt < 4; mt++) {
            int row0 = rowBase + wm * 64 + mt * 16 + g;
#pragma unroll
            for (int nt = 0; nt < 4; nt++) {
                int col = wn * 32 + nt * 8 + t2;
                if (row0 < M)
                    *(float2*)&HP3[(size_t)row0 * 256 + col] =
                        make_float2(acc2[mt][nt][0], acc2[mt][nt][1]);
                if (row0 + 8 < M)
                    *(float2*)&HP3[(size_t)(row0 + 8) * 256 + col] =
                        make_float2(acc2[mt][nt][2], acc2[mt][nt][3]);
            }
        }
    }
}

// ---------------- launch --------------------------------------------------------------
extern "C" void kernel_launch(void* const* d_in, const int* in_sizes, int n_in,
                              void* d_out, int out_size) {
    const float* features = (const float*)d_in[0];  // [N, 512]
    const float* W1       = (const float*)d_in[1];  // [512, 256]
    const float* W2       = (const float*)d_in[2];  // [256, 64]
    const float* att_src  = (const float*)d_in[3];  // [256]
    const float* att_dst  = (const float*)d_in[4];  // [256]
    const int*   edge     = (const int*)d_in[5];    // [2, E]
    const int* src = edge;
    const int* dst = edge + E_EDGES;

    float* out = (float*)d_out;
    float* h2 = out;                              // [N, 64]
    float* h4 = out + (size_t)N_NODES * OUT_DIM_; // [N, 512]

    float *hp1, *h1acc, *hp3, *a_s, *a_d;
    cudaGetSymbolAddress((void**)&hp1,   g_hp1);
    cudaGetSymbolAddress((void**)&h1acc, g_h1acc);
    cudaGetSymbolAddress((void**)&hp3,   g_hp3);
    cudaGetSymbolAddress((void**)&a_s,   g_as);
    cudaGetSymbolAddress((void**)&a_d,   g_ad);

    int *deg, *start, *cursor, *csr_src;
    float* csr_w;
    cudaGetSymbolAddress((void**)&deg,     g_deg);
    cudaGetSymbolAddress((void**)&start,   g_start);
    cudaGetSymbolAddress((void**)&cursor,  g_cursor);
    cudaGetSymbolAddress((void**)&csr_src, g_csr_src);
    cudaGetSymbolAddress((void**)&csr_w,   g_csr_w);

    __nv_bfloat16 *b1hi, *b1lo, *b2hi, *b2lo, *b3hi, *b3lo, *b4hi, *b4lo;
    cudaGetSymbolAddress((void**)&b1hi, g_b1hi); cudaGetSymbolAddress((void**)&b1lo, g_b1lo);
    cudaGetSymbolAddress((void**)&b2hi, g_b2hi); cudaGetSymbolAddress((void**)&b2lo, g_b2lo);
    cudaGetSymbolAddress((void**)&b3hi, g_b3hi); cudaGetSymbolAddress((void**)&b3lo, g_b3lo);
    cudaGetSymbolAddress((void**)&b4hi, g_b4hi); cudaGetSymbolAddress((void**)&b4lo, g_b4lo);

    const int smem128 = 4 * 10240 + 4 * 128 * 40 * 2;  // 81920
    const int smem23  = 110592;
    cudaFuncSetAttribute(hmma_gemm<128, false, true>,
                         cudaFuncAttributeMaxDynamicSharedMemorySize, smem128);
    cudaFuncSetAttribute(hmma_gemm<128, true, false>,
                         cudaFuncAttributeMaxDynamicSharedMemorySize, smem128);
    cudaFuncSetAttribute(gemm23_fused,
                         cudaFuncAttributeMaxDynamicSharedMemorySize, smem23);

    const int mtiles = (N_NODES + 127) / 128;  // 391
    const int nodeWarpGrid = (N_NODES * 32 + 255) / 256;

    // fork a side stream for the CSR build (independent of GEMM1 chain)
    cudaStream_t s2;
    cudaStreamCreateWithFlags(&s2, cudaStreamNonBlocking);
    cudaEvent_t e1, e2;
    cudaEventCreateWithFlags(&e1, cudaEventDisableTiming);
    cudaEventCreateWithFlags(&e2, cudaEventDisableTiming);

    cudaEventRecord(e1, 0);
    cudaStreamWaitEvent(s2, e1, 0);
    zero_deg<<<(N_NODES + 255) / 256, 256, 0, s2>>>(deg);
    count_deg<<<(E_EDGES + 255) / 256, 256, 0, s2>>>(dst, deg);
    scan_deg<<<1, 1024, 0, s2>>>(deg, start, cursor);
    fill_csr<<<(E_EDGES + 255) / 256, 256, 0, s2>>>(src, dst, cursor, csr_src);
    cudaEventRecord(e2, s2);

    // main chain
    prep_weights<<<(512 * 256 + 255) / 256, 256>>>(W1, W2, b1hi, b1lo, b2hi, b2lo,
                                                   b3hi, b3lo, b4hi, b4lo, a_s, a_d);
    hmma_gemm<128, false, true><<<dim3(2, mtiles), 512, smem128>>>(
        features, b1hi, b1lo, hp1, N_NODES, HID_, IN_DIM_, att_src, att_dst, a_s, a_d);

    cudaStreamWaitEvent(0, e2, 0);  // join CSR branch

    softmax_prop<<<nodeWarpGrid, 256>>>(start, deg, csr_src, a_s, a_d, csr_w, hp1, h1acc);
    gemm23_fused<<<dim3(1, mtiles), 512, smem23>>>(h1acc, b2hi, b2lo, b3hi, b3lo,
                                                   h2, hp3, N_NODES);
    propagate_csr<<<nodeWarpGrid, 256>>>(start, deg, csr_src, csr_w, hp3, h1acc);
    hmma_gemm<128, true, false><<<dim3(4, mtiles), 512, smem128>>>(
        h1acc, b4hi, b4lo, h4, N_NODES, IN_DIM_, HID_, nullptr, nullptr, nullptr, nullptr);

    (void)in_sizes; (void)n_in; (void)out_size;
}